// round 7
// baseline (speedup 1.0000x reference)
#include <cuda_runtime.h>
#include <cuda_bf16.h>
#include <math.h>
#include <stdint.h>

#define BB 8
#define CCH 128
#define HH 128
#define WW 128
#define HWP (HH*WW)
#define RRAD 4

// ---------------- scratch (device globals; no allocation allowed) -------------
__device__ float g_x1[BB*CCH*HWP];     // conv1 out (fp32, pre-GN)
__device__ float g_x2[BB*64*HWP];      // conv2 out
__device__ float g_pred[BB*3*HWP];     // conv3 out (flow + validity logit)
__device__ float g_cv[BB*81*HWP];      // cost volume
__device__ float g_cd[BB*CCH*HWP];     // ce (ch 0-63) + de (ch 64-127), pre-GN
__device__ float g_f[BB*CCH*HWP];      // fus1 out (raw, pre-GN)
__device__ float g_weff[CCH];          // fused fus_w2 -> lam weight
__device__ float g_red[5*256*2];       // 5 GN sites x (B*32 groups) x (sum, sumsq)
__device__ float g_stats[5*256*2];     // 5 GN sites x (B*32 groups) x (mean, rstd)

// packed bf16 hi/lo activations: [b][ch16][y][x][c16]
__device__ __nv_bfloat16 g_a1h[(size_t)BB*16*HWP*16], g_a1l[(size_t)BB*16*HWP*16]; // conv1 in (256ch)
__device__ __nv_bfloat16 g_a2h[(size_t)BB*8*HWP*16],  g_a2l[(size_t)BB*8*HWP*16];  // conv2 in (128ch)
__device__ __nv_bfloat16 g_a3h[(size_t)BB*8*HWP*16],  g_a3l[(size_t)BB*8*HWP*16];  // fus1 in (128ch)

// bf16-split weights, pre-permuted: [cin_chunk][tap(9)][cout_all][cin16]
#define WOFF1 0
#define WOFF2 294912            // conv1: 128*256*9
#define WOFFF (294912 + 73728)  // conv2: 64*128*9
#define WTOT  (294912 + 73728 + 147456)
__device__ __nv_bfloat16 g_wh[WTOT];
__device__ __nv_bfloat16 g_wl[WTOT];

#define ALIGNED_OFF 0
#define FLOW_OFF (BB*CCH*HWP)
#define LAM_OFF  (FLOW_OFF + BB*2*HWP)

// ---------------- mma / cp.async helpers --------------------------------------
__device__ __forceinline__ void ldsm4(uint32_t& r0, uint32_t& r1, uint32_t& r2, uint32_t& r3,
                                      uint32_t addr) {
    asm volatile("ldmatrix.sync.aligned.m8n8.x4.shared.b16 {%0,%1,%2,%3},[%4];"
        : "=r"(r0), "=r"(r1), "=r"(r2), "=r"(r3) : "r"(addr));
}
__device__ __forceinline__ void mma16816(float* c, const uint32_t* a, const uint32_t* b) {
    asm volatile("mma.sync.aligned.m16n8k16.row.col.f32.bf16.bf16.f32 "
        "{%0,%1,%2,%3},{%4,%5,%6,%7},{%8,%9},{%0,%1,%2,%3};"
        : "+f"(c[0]), "+f"(c[1]), "+f"(c[2]), "+f"(c[3])
        : "r"(a[0]), "r"(a[1]), "r"(a[2]), "r"(a[3]), "r"(b[0]), "r"(b[1]));
}
__device__ __forceinline__ void cpasync16(uint32_t dst, const void* src) {
    asm volatile("cp.async.cg.shared.global [%0],[%1],16;" :: "r"(dst), "l"(src));
}
__device__ __forceinline__ void cpcommit() { asm volatile("cp.async.commit_group;"); }
template<int N> __device__ __forceinline__ void cpwait() {
    asm volatile("cp.async.wait_group %0;" :: "n"(N));
}

// ---------------- zero the reduction buffer -----------------------------------
__global__ void zero_red_k(float* __restrict__ red)
{
    int i = blockIdx.x*512 + threadIdx.x*2;
    red[i] = 0.f;
    red[i+1] = 0.f;
}

// ---------------- finalize: (sum, sumsq) -> (mean, rstd) ----------------------
__global__ void finalize_k(const float* __restrict__ red, float* __restrict__ stats, int N)
{
    int i = threadIdx.x;   // 256 = b*32+g
    float invN = 1.f / (float)N;
    float m = red[i*2] * invN;
    float var = red[i*2+1]*invN - m*m;
    stats[i*2]   = m;
    stats[i*2+1] = rsqrtf(fmaxf(var, 0.f) + 1e-5f);
}

// ---------------- weight prep: fp32 [COUT][CIN][9] -> split bf16 permuted -----
__global__ void wprep_k(const float* __restrict__ w, __nv_bfloat16* __restrict__ wh,
                        __nv_bfloat16* __restrict__ wl, int COUT, int CIN)
{
    int idx = blockIdx.x*256 + threadIdx.x;
    int total = COUT*CIN*9;
    if (idx >= total) return;
    int c16 = idx & 15;
    int co  = (idx >> 4) % COUT;
    int rest = (idx >> 4) / COUT;    // ch*9 + tap
    int tap = rest % 9;
    int ch = rest / 9;
    int cin = ch*16 + c16;
    float v = w[((size_t)co*CIN + cin)*9 + tap];
    __nv_bfloat16 h = __float2bfloat16(v);
    wh[idx] = h;
    wl[idx] = __float2bfloat16(v - __bfloat162float(h));
}

// ---------------- pack feat1+feat2 -> bf16 hi/lo packed (one launch) ----------
__global__ void pack2_k(const float* __restrict__ src1, const float* __restrict__ src2,
                        __nv_bfloat16* __restrict__ dh, __nv_bfloat16* __restrict__ dl)
{
    int p = blockIdx.x*256 + threadIdx.x;
    int by = blockIdx.y, b = blockIdx.z;          // by 0..15
    const float* src = (by < 8) ? src1 : src2;
    int cb = (by & 7)*16;
    union { uint4 u[2]; __nv_bfloat16 h[16]; } ph, pl;
    #pragma unroll
    for (int c = 0; c < 16; c++) {
        float v = src[((size_t)(b*128 + cb + c))*HWP + p];
        __nv_bfloat16 hh = __float2bfloat16(v);
        ph.h[c] = hh;
        pl.h[c] = __float2bfloat16(v - __bfloat162float(hh));
    }
    size_t e = (((size_t)(b*16 + by))*HWP + p)*16;
    ((uint4*)(dh + e))[0] = ph.u[0]; ((uint4*)(dh + e))[1] = ph.u[1];
    ((uint4*)(dl + e))[0] = pl.u[0]; ((uint4*)(dl + e))[1] = pl.u[1];
}

// ---------------- GN apply + act -> bf16 hi/lo packed -------------------------
__global__ void gn_apply_pack_k(const float* __restrict__ x, const float* __restrict__ gamma,
                                const float* __restrict__ beta, const float* __restrict__ stats,
                                int Ctot, int c_off_src, int cpg, int act,
                                __nv_bfloat16* __restrict__ dh, __nv_bfloat16* __restrict__ dl,
                                int ch_off, int NCHT)
{
    int p = blockIdx.x*256 + threadIdx.x;
    int by = blockIdx.y, b = blockIdx.z;
    union { uint4 u[2]; __nv_bfloat16 h[16]; } ph, pl;
    #pragma unroll
    for (int c = 0; c < 16; c++) {
        int cl = by*16 + c;
        int g = cl / cpg;
        float m = stats[(b*32 + g)*2];
        float r = stats[(b*32 + g)*2 + 1];
        float v = x[((size_t)(b*Ctot + c_off_src + cl))*HWP + p];
        v = (v - m) * r * gamma[cl] + beta[cl];
        if (act == 0) v = v / (1.f + expf(-v));
        else          v = fmaxf(v, 0.f);
        __nv_bfloat16 hh = __float2bfloat16(v);
        ph.h[c] = hh;
        pl.h[c] = __float2bfloat16(v - __bfloat162float(hh));
    }
    size_t e = (((size_t)(b*NCHT + ch_off + by))*HWP + p)*16;
    ((uint4*)(dh + e))[0] = ph.u[0]; ((uint4*)(dh + e))[1] = ph.u[1];
    ((uint4*)(dl + e))[0] = pl.u[0]; ((uint4*)(dl + e))[1] = pl.u[1];
}

// ---------------- tensor-core 3x3 conv, cp.async pipelined, fused GN-reduce ---
template<int NCH, int COUTB>
__global__ void __launch_bounds__(256)
conv3x3_mma_k(const __nv_bfloat16* __restrict__ aph, const __nv_bfloat16* __restrict__ apl,
              const __nv_bfloat16* __restrict__ gwh, const __nv_bfloat16* __restrict__ gwl,
              float* __restrict__ out, int COUT, float* __restrict__ red, int cpgshift)
{
    const int MF = COUTB/32;
    const int WPL = 9*COUTB*16;               // weight plane, elements
    const int WPLB = WPL*2;                   // weight plane, bytes
    const int WBUF = 2*WPLB;                  // one weight buffer (hi+lo), bytes
    const int APLB = 5440*2;                  // act plane bytes
    const int ABUF = 2*APLB;                  // one act buffer (hi+lo), bytes
    const int ABASE = 2*WBUF;
    extern __shared__ char dsm[];

    int b = blockIdx.z, tile = blockIdx.x;
    int X0 = (tile & 3) * 32;
    int Y0 = (tile >> 2) * 8;
    int tid = threadIdx.x;
    int wid = tid >> 5, lane = tid & 31;
    int cw = wid & 1, pw = wid >> 1;
    int g = lane >> 2, t = lane & 3;

    uint32_t sm_base = (uint32_t)__cvta_generic_to_shared(dsm);

    float acc[MF][8][4];
    #pragma unroll
    for (int mf = 0; mf < MF; mf++)
        #pragma unroll
        for (int j = 0; j < 8; j++)
            #pragma unroll
            for (int k = 0; k < 4; k++) acc[mf][j][k] = 0.f;

    int m = lane >> 3, ri = lane & 7;
    int a_kb = (m >> 1) * 8;
    int a_corow = (m & 1) * 8 + ri;
    uint32_t b_off[4];
    {
        int mm = lane >> 3;
        int rb = lane & 7;
        #pragma unroll
        for (int jp = 0; jp < 4; jp++) {
            int j = jp*2 + (mm >> 1);
            int kb = (mm & 1) * 8;
            int n = j*8 + rb;
            int rloc = n >> 5, xb = n & 31;
            b_off[jp] = (uint32_t)((((pw*2 + rloc)*34 + xb)*16 + kb) * 2);
        }
    }

    auto stage = [&](int ch, int bf) {
        const char* sh = (const char*)(gwh + (size_t)ch*WPL);
        const char* sl = (const char*)(gwl + (size_t)ch*WPL);
        uint32_t wd = sm_base + bf*WBUF;
        const int NV = WPLB/16;
        for (int i = tid; i < NV; i += 256) {
            cpasync16(wd + i*16, sh + i*16);
            cpasync16(wd + WPLB + i*16, sl + i*16);
        }
        uint32_t ad = sm_base + ABASE + bf*ABUF;
        uint4* dah = (uint4*)(dsm + ABASE + bf*ABUF);
        uint4* dal = (uint4*)(dsm + ABASE + bf*ABUF + APLB);
        const uint4 z = make_uint4(0,0,0,0);
        size_t basee = ((size_t)(b*NCH + ch))*HWP;
        for (int i = tid; i < 680; i += 256) {
            int pos = i >> 1, half = i & 1;
            int r = pos / 34, col = pos % 34;
            int gy = Y0 + r - 1, gx = X0 + col - 1;
            if (gy >= 0 && gy < HH && gx >= 0 && gx < WW) {
                size_t e = (basee + gy*WW + gx)*16 + half*8;
                cpasync16(ad + (pos*2 + half)*16, aph + e);
                cpasync16(ad + APLB + (pos*2 + half)*16, apl + e);
            } else {
                dah[pos*2 + half] = z;
                dal[pos*2 + half] = z;
            }
        }
    };

    stage(0, 0);
    cpcommit();

    for (int ch = 0; ch < NCH; ch++) {
        if (ch + 1 < NCH) { stage(ch + 1, (ch + 1) & 1); cpcommit(); cpwait<1>(); }
        else              { cpwait<0>(); }
        __syncthreads();

        int bf = ch & 1;
        uint32_t swb = sm_base + bf*WBUF;
        uint32_t sab = sm_base + ABASE + bf*ABUF;

        #pragma unroll
        for (int tap = 0; tap < 9; tap++) {
            int ky = tap / 3, kx = tap - ky*3;
            uint32_t ah[MF][4], al[MF][4];
            #pragma unroll
            for (int mf = 0; mf < MF; mf++) {
                uint32_t off = (uint32_t)(((tap*COUTB + cw*(COUTB/2) + mf*16 + a_corow)*16 + a_kb) * 2);
                ldsm4(ah[mf][0], ah[mf][1], ah[mf][2], ah[mf][3], swb + off);
                ldsm4(al[mf][0], al[mf][1], al[mf][2], al[mf][3], swb + (uint32_t)WPLB + off);
            }
            uint32_t tshift = (uint32_t)(((ky*34 + kx)*16) * 2);
            #pragma unroll
            for (int jp = 0; jp < 4; jp++) {
                uint32_t ba = sab + b_off[jp] + tshift;
                uint32_t bh[4], bl[4];
                ldsm4(bh[0], bh[1], bh[2], bh[3], ba);
                ldsm4(bl[0], bl[1], bl[2], bl[3], ba + (uint32_t)APLB);
                #pragma unroll
                for (int jj = 0; jj < 2; jj++) {
                    int j = jp*2 + jj;
                    #pragma unroll
                    for (int mf = 0; mf < MF; mf++) {
                        mma16816(acc[mf][j], ah[mf], &bh[jj*2]);
                        mma16816(acc[mf][j], ah[mf], &bl[jj*2]);
                        mma16816(acc[mf][j], al[mf], &bh[jj*2]);
                    }
                }
            }
        }
        __syncthreads();
    }

    // ---- fused GN partial reduction (sum, sumsq per group) ----
    {
        float* bins = (float*)dsm;    // 64 floats: 32 groups x (sum, sumsq)
        if (tid < 64) bins[tid] = 0.f;
        __syncthreads();
        #pragma unroll
        for (int mf = 0; mf < MF; mf++) {
            int cout0 = cw*(COUTB/2) + mf*16 + g;
            float s0 = 0.f, q0 = 0.f, s1 = 0.f, q1 = 0.f;
            #pragma unroll
            for (int j = 0; j < 8; j++) {
                s0 += acc[mf][j][0] + acc[mf][j][1];
                q0 += acc[mf][j][0]*acc[mf][j][0] + acc[mf][j][1]*acc[mf][j][1];
                s1 += acc[mf][j][2] + acc[mf][j][3];
                q1 += acc[mf][j][2]*acc[mf][j][2] + acc[mf][j][3]*acc[mf][j][3];
            }
            int g0 = cout0 >> cpgshift, g1 = (cout0 + 8) >> cpgshift;
            atomicAdd(&bins[g0*2],   s0);
            atomicAdd(&bins[g0*2+1], q0);
            atomicAdd(&bins[g1*2],   s1);
            atomicAdd(&bins[g1*2+1], q1);
        }
        __syncthreads();
        if (tid < 64) atomicAdd(&red[(b*32 + (tid>>1))*2 + (tid&1)], bins[tid]);
    }

    // ---- writeback ----
    #pragma unroll
    for (int mf = 0; mf < MF; mf++)
        #pragma unroll
        for (int j = 0; j < 8; j++) {
            int n0 = j*8 + 2*t;
            int rloc = n0 >> 5, x = n0 & 31;
            int py = Y0 + pw*2 + rloc, px = X0 + x;
            int cout0 = cw*(COUTB/2) + mf*16 + g;
            float2 v01 = make_float2(acc[mf][j][0], acc[mf][j][1]);
            float2 v23 = make_float2(acc[mf][j][2], acc[mf][j][3]);
            *(float2*)&out[((size_t)(b*COUT + cout0))*HWP + py*WW + px] = v01;
            *(float2*)&out[((size_t)(b*COUT + cout0 + 8))*HWP + py*WW + px] = v23;
        }
}

// ---------------- conv3: 64 -> 3, 3x3 pad=1, + bias ---------------------------
__global__ void conv3_k(const float* __restrict__ x, const float* __restrict__ w,
                        const float* __restrict__ bias, float* __restrict__ pred)
{
    const int CK = 8;
    __shared__ float s_in[CK][18][20];
    __shared__ float s_w[CK][9][4];
    int b = blockIdx.z;
    int X0 = (blockIdx.x & 7) * 16;
    int Y0 = (blockIdx.x >> 3) * 16;
    int tid = threadIdx.x;
    int ty = tid >> 4, tx = tid & 15;
    float acc[3] = {0.f, 0.f, 0.f};

    for (int c0 = 0; c0 < 64; c0 += CK) {
        for (int i = tid; i < CK*18*18; i += 256) {
            int c = i / 324, rem = i % 324, r = rem / 18, col = rem % 18;
            int gy = Y0 + r - 1, gx = X0 + col - 1;
            float v = 0.f;
            if (gy >= 0 && gy < HH && gx >= 0 && gx < WW)
                v = x[((size_t)(b*64 + c0 + c))*HWP + gy*WW + gx];
            s_in[c][r][col] = v;
        }
        for (int i = tid; i < CK*9*3; i += 256) {
            int c = i / 27, rem = i % 27, tap = rem / 3, o = rem % 3;
            s_w[c][tap][o] = w[(size_t)o*64*9 + (c0 + c)*9 + tap];
        }
        __syncthreads();
        #pragma unroll
        for (int c = 0; c < CK; c++)
            #pragma unroll
            for (int ky = 0; ky < 3; ky++)
                #pragma unroll
                for (int kx = 0; kx < 3; kx++) {
                    float v = s_in[c][ty + ky][tx + kx];
                    acc[0] += v * s_w[c][ky*3 + kx][0];
                    acc[1] += v * s_w[c][ky*3 + kx][1];
                    acc[2] += v * s_w[c][ky*3 + kx][2];
                }
        __syncthreads();
    }
    int p = (Y0 + ty)*WW + X0 + tx;
    pred[(size_t)(b*3 + 0)*HWP + p] = acc[0] + bias[0];
    pred[(size_t)(b*3 + 1)*HWP + p] = acc[1] + bias[1];
    pred[(size_t)(b*3 + 2)*HWP + p] = acc[2] + bias[2];
}

// ---------------- GroupNorm apply + act, fp32 in-place ------------------------
__global__ void gn_apply_k(float* __restrict__ x, const float* __restrict__ gamma,
                           const float* __restrict__ beta, const float* __restrict__ stats,
                           int Ctot, int c_off, int Csub, int cpg, int act)
{
    int idx = blockIdx.x*256 + threadIdx.x;
    int total = BB*Csub*HWP;
    if (idx >= total) return;
    int p = idx % HWP;
    int c = (idx / HWP) % Csub;
    int b = idx / (Csub*HWP);
    int g = c / cpg;
    float m = stats[(b*32 + g)*2];
    float r = stats[(b*32 + g)*2 + 1];
    size_t a = ((size_t)(b*Ctot + c_off + c))*HWP + p;
    float v = (x[a] - m) * r * gamma[c] + beta[c];
    if (act == 0) v = v / (1.f + expf(-v));
    else          v = fmaxf(v, 0.f);
    x[a] = v;
}

// ---------------- bilinear warp * validity; also writes flow ------------------
__global__ void warp_k(const float* __restrict__ feat2, const float* __restrict__ pred,
                       float* __restrict__ out)
{
    int idx = blockIdx.x*256 + threadIdx.x;
    int b = idx / HWP, p = idx % HWP;
    int yi = p / WW, xi = p % WW;
    float fx = pred[(size_t)(b*3 + 0)*HWP + p];
    float fy = pred[(size_t)(b*3 + 1)*HWP + p];
    float vl = pred[(size_t)(b*3 + 2)*HWP + p];
    float vald = 1.f / (1.f + expf(-vl));
    float px = xi + fx, py = yi + fy;
    float x0 = floorf(px), y0 = floorf(py);
    float wx = px - x0, wy = py - y0;

    float cx[2] = {x0, x0 + 1.f};
    float cy[2] = {y0, y0 + 1.f};
    float vxf[2], vyf[2];
    int xcl[2], ycl[2];
    #pragma unroll
    for (int k = 0; k < 2; k++) {
        vxf[k] = (cx[k] >= 0.f && cx[k] <= (float)(WW - 1)) ? 1.f : 0.f;
        vyf[k] = (cy[k] >= 0.f && cy[k] <= (float)(HH - 1)) ? 1.f : 0.f;
        int xv = (int)cx[k]; xv = xv < 0 ? 0 : (xv > WW-1 ? WW-1 : xv); xcl[k] = xv;
        int yv = (int)cy[k]; yv = yv < 0 ? 0 : (yv > HH-1 ? HH-1 : yv); ycl[k] = yv;
    }
    float wv[4];
    wv[0] = (1.f - wx)*(1.f - wy) * vxf[0]*vyf[0];
    wv[1] = wx*(1.f - wy)         * vxf[1]*vyf[0];
    wv[2] = (1.f - wx)*wy         * vxf[0]*vyf[1];
    wv[3] = wx*wy                 * vxf[1]*vyf[1];
    int off[4];
    off[0] = ycl[0]*WW + xcl[0];
    off[1] = ycl[0]*WW + xcl[1];
    off[2] = ycl[1]*WW + xcl[0];
    off[3] = ycl[1]*WW + xcl[1];

    const float* f2b = feat2 + (size_t)b*CCH*HWP;
    #pragma unroll 4
    for (int c = 0; c < CCH; c++) {
        const float* fc = f2b + (size_t)c*HWP;
        float v = wv[0]*fc[off[0]] + wv[1]*fc[off[1]] + wv[2]*fc[off[2]] + wv[3]*fc[off[3]];
        out[ALIGNED_OFF + ((size_t)(b*CCH + c))*HWP + p] = v * vald;
    }
    out[FLOW_OFF + (size_t)(b*2 + 0)*HWP + p] = fx;
    out[FLOW_OFF + (size_t)(b*2 + 1)*HWP + p] = fy;
}

// ---------------- cost volume: one pass, all 81 offsets -----------------------
__global__ void __launch_bounds__(256) costvol_k(const float* __restrict__ f1,
                                                 const float* __restrict__ al,
                                                 float* __restrict__ cv)
{
    const int CK = 4;
    __shared__ float s_f1[CK][16][16];
    __shared__ float s_al[CK][24][24];
    int b = blockIdx.z;
    int tile = blockIdx.x;
    int X0 = (tile & 7) * 16;
    int Y0 = (tile >> 3) * 16;
    int tid = threadIdx.x;
    int ty = tid >> 4, tx = tid & 15;
    float acc[81];
    #pragma unroll
    for (int d = 0; d < 81; d++) acc[d] = 0.f;

    for (int c0 = 0; c0 < CCH; c0 += CK) {
        for (int i = tid; i < CK*256; i += 256) {
            int c = i >> 8, r = (i >> 4) & 15, col = i & 15;
            s_f1[c][r][col] = f1[((size_t)(b*CCH + c0 + c))*HWP + (Y0 + r)*WW + X0 + col];
        }
        for (int i = tid; i < CK*576; i += 256) {
            int c = i / 576, rem = i % 576, r = rem / 24, col = rem % 24;
            int gy = Y0 + r - RRAD;
            int gx = X0 + col - RRAD;
            float v = 0.f;
            if (gy >= 0 && gy < HH && gx >= 0 && gx < WW)
                v = al[((size_t)(b*CCH + c0 + c))*HWP + gy*WW + gx];
            s_al[c][r][col] = v;
        }
        __syncthreads();
        #pragma unroll
        for (int c = 0; c < CK; c++) {
            float f = s_f1[c][ty][tx];
            #pragma unroll
            for (int dy = 0; dy < 9; dy++)
                #pragma unroll
                for (int dx = 0; dx < 9; dx++)
                    acc[dy*9 + dx] += f * s_al[c][ty + dy][tx + dx];
        }
        __syncthreads();
    }
    int p = (Y0 + ty)*WW + X0 + tx;
    #pragma unroll
    for (int d = 0; d < 81; d++)
        cv[((size_t)(b*81 + d))*HWP + p] = acc[d] * (1.0f/CCH);
}

// ---------------- 1x1 conv + fused GN reduce (MODE 0 plain, 1 |A-B|) ----------
template<int CIN, int MODE>
__global__ void conv1x1_k(const float* __restrict__ inA, const float* __restrict__ inB,
                          const float* __restrict__ wgt, float* __restrict__ out, int c_off,
                          float* __restrict__ red)
{
    const int CK = 8;
    __shared__ float s_w[CK][64];
    __shared__ float s_x[CK][128];
    __shared__ float bins[64];
    int tid = threadIdx.x;
    int P0 = blockIdx.x * 128;
    int b = P0 / HWP;
    int p0 = P0 % HWP;
    int co_g = tid >> 5;
    int pg = tid & 31;
    float acc[8][4];
    #pragma unroll
    for (int k = 0; k < 8; k++)
        #pragma unroll
        for (int j = 0; j < 4; j++) acc[k][j] = 0.f;
    if (tid < 64) bins[tid] = 0.f;

    for (int c0 = 0; c0 < CIN; c0 += CK) {
        for (int i = tid; i < CK*64; i += 256) {
            int c = i >> 6, o = i & 63;
            int ci = c0 + c;
            s_w[c][o] = (ci < CIN) ? wgt[(size_t)o*CIN + ci] : 0.f;
        }
        for (int i = tid; i < CK*128; i += 256) {
            int c = i >> 7, px = i & 127;
            int ci = c0 + c;
            float v = 0.f;
            if (ci < CIN) {
                if (MODE == 0) {
                    v = inA[((size_t)(b*CIN + ci))*HWP + p0 + px];
                } else {
                    size_t gi = ((size_t)(b*CCH + ci))*HWP + p0 + px;
                    v = fabsf(inA[gi] - inB[gi]);
                }
            }
            s_x[c][px] = v;
        }
        __syncthreads();
        #pragma unroll
        for (int c = 0; c < CK; c++) {
            float4 wa = *(const float4*)&s_w[c][co_g*8];
            float4 wb = *(const float4*)&s_w[c][co_g*8 + 4];
            float4 x4 = *(const float4*)&s_x[c][pg*4];
            float w8[8] = {wa.x, wa.y, wa.z, wa.w, wb.x, wb.y, wb.z, wb.w};
            float xv[4] = {x4.x, x4.y, x4.z, x4.w};
            #pragma unroll
            for (int k = 0; k < 8; k++)
                #pragma unroll
                for (int j = 0; j < 4; j++) acc[k][j] += w8[k]*xv[j];
        }
        __syncthreads();
    }
    #pragma unroll
    for (int k = 0; k < 8; k++) {
        int cl = co_g*8 + k;
        float s = acc[k][0]+acc[k][1]+acc[k][2]+acc[k][3];
        float q = acc[k][0]*acc[k][0]+acc[k][1]*acc[k][1]+acc[k][2]*acc[k][2]+acc[k][3]*acc[k][3];
        atomicAdd(&bins[(cl>>1)*2],   s);
        atomicAdd(&bins[(cl>>1)*2+1], q);
        int oc = c_off + cl;
        float4 r4 = make_float4(acc[k][0], acc[k][1], acc[k][2], acc[k][3]);
        *(float4*)&out[((size_t)(b*CCH + oc))*HWP + p0 + pg*4] = r4;
    }
    __syncthreads();
    if (tid < 64) atomicAdd(&red[(b*32 + (tid>>1))*2 + (tid&1)], bins[tid]);
}

// ---------------- fused fus_w2 -> lam weight ----------------------------------
__global__ void weff_k(const float* __restrict__ fus_w2, const float* __restrict__ lam_w,
                       float* __restrict__ weff)
{
    int c = threadIdx.x;
    float s = 0.f;
    for (int o = 0; o < 128; o++) s += lam_w[o] * fus_w2[(size_t)o*128 + c];
    weff[c] = s;
}

// ---------------- lam = sigmoid(dot(weff, relu(GN(f))) + lam_b) ---------------
__global__ void lam_gn_k(const float* __restrict__ f, const float* __restrict__ weff,
                         const float* __restrict__ gamma, const float* __restrict__ beta,
                         const float* __restrict__ stats, const float* __restrict__ lam_b,
                         float* __restrict__ out)
{
    __shared__ float sw[128], sa[128], sb[128];
    int tid = threadIdx.x;
    int idx = blockIdx.x*256 + tid;
    int b = idx / HWP, p = idx % HWP;
    if (tid < 128) {
        int c = tid;
        float mm = stats[(b*32 + c/4)*2];
        float rr = stats[(b*32 + c/4)*2 + 1];
        float ga = gamma[c]*rr;
        sw[c] = weff[c];
        sa[c] = ga;
        sb[c] = beta[c] - mm*ga;
    }
    __syncthreads();
    float s = lam_b[0];
    const float* fb = f + (size_t)b*CCH*HWP + p;
    #pragma unroll 4
    for (int c = 0; c < CCH; c++) {
        float v = fmaxf(fmaf(fb[(size_t)c*HWP], sa[c], sb[c]), 0.f);
        s = fmaf(sw[c], v, s);
    }
    out[LAM_OFF + idx] = 1.f / (1.f + expf(-s));
}

// ---------------- launch ------------------------------------------------------
extern "C" void kernel_launch(void* const* d_in, const int* in_sizes, int n_in,
                              void* d_out, int out_size)
{
    const float* feat1    = (const float*)d_in[0];
    const float* feat2    = (const float*)d_in[1];
    const float* off_w1   = (const float*)d_in[2];
    const float* off_g1   = (const float*)d_in[3];
    const float* off_b1   = (const float*)d_in[4];
    const float* off_w2   = (const float*)d_in[5];
    const float* off_g2   = (const float*)d_in[6];
    const float* off_b2   = (const float*)d_in[7];
    const float* off_w3   = (const float*)d_in[8];
    const float* off_bias3= (const float*)d_in[9];
    const float* corr_w   = (const float*)d_in[10];
    const float* corr_g   = (const float*)d_in[11];
    const float* corr_b   = (const float*)d_in[12];
    const float* diff_w   = (const float*)d_in[13];
    const float* diff_g   = (const float*)d_in[14];
    const float* diff_b   = (const float*)d_in[15];
    const float* fus_w1   = (const float*)d_in[16];
    const float* fus_g1   = (const float*)d_in[17];
    const float* fus_b1   = (const float*)d_in[18];
    const float* fus_w2   = (const float*)d_in[19];
    const float* lam_w    = (const float*)d_in[20];
    const float* lam_b    = (const float*)d_in[21];
    float* out = (float*)d_out;

    float *x1, *x2, *pred, *cv, *cd, *f, *weff, *red, *stats;
    __nv_bfloat16 *wh, *wl, *a1h, *a1l, *a2h, *a2l, *a3h, *a3l;
    cudaGetSymbolAddress((void**)&x1,   g_x1);
    cudaGetSymbolAddress((void**)&x2,   g_x2);
    cudaGetSymbolAddress((void**)&pred, g_pred);
    cudaGetSymbolAddress((void**)&cv,   g_cv);
    cudaGetSymbolAddress((void**)&cd,   g_cd);
    cudaGetSymbolAddress((void**)&f,    g_f);
    cudaGetSymbolAddress((void**)&weff, g_weff);
    cudaGetSymbolAddress((void**)&red,  g_red);
    cudaGetSymbolAddress((void**)&stats,g_stats);
    cudaGetSymbolAddress((void**)&wh,   g_wh);
    cudaGetSymbolAddress((void**)&wl,   g_wl);
    cudaGetSymbolAddress((void**)&a1h,  g_a1h);
    cudaGetSymbolAddress((void**)&a1l,  g_a1l);
    cudaGetSymbolAddress((void**)&a2h,  g_a2h);
    cudaGetSymbolAddress((void**)&a2l,  g_a2l);
    cudaGetSymbolAddress((void**)&a3h,  g_a3h);
    cudaGetSymbolAddress((void**)&a3l,  g_a3l);

    const int SMEM_128 = 2*(2*9*128*16*2) + 2*(2*5440*2);   // 190976
    const int SMEM_64  = 2*(2*9*64*16*2)  + 2*(2*5440*2);   // 117248
    cudaFuncSetAttribute(conv3x3_mma_k<16,128>, cudaFuncAttributeMaxDynamicSharedMemorySize, SMEM_128);
    cudaFuncSetAttribute(conv3x3_mma_k<8,128>,  cudaFuncAttributeMaxDynamicSharedMemorySize, SMEM_128);
    cudaFuncSetAttribute(conv3x3_mma_k<8,64>,   cudaFuncAttributeMaxDynamicSharedMemorySize, SMEM_64);

    // zero GN reduction buffer (5*256*2 = 2560 = 5 blocks * 256 thr * 2)
    zero_red_k<<<5, 256>>>(red);

    // weight prep
    wprep_k<<<(128*256*9 + 255)/256, 256>>>(off_w1, wh + WOFF1, wl + WOFF1, 128, 256);
    wprep_k<<<( 64*128*9 + 255)/256, 256>>>(off_w2, wh + WOFF2, wl + WOFF2,  64, 128);
    wprep_k<<<(128*128*9 + 255)/256, 256>>>(fus_w1, wh + WOFFF, wl + WOFFF, 128, 128);

    // pack conv1 inputs (feat1 -> groups 0..7, feat2 -> 8..15), one launch
    pack2_k<<<dim3(HWP/256, 16, BB), 256>>>(feat1, feat2, a1h, a1l);

    // conv1 (256 -> 128) + fused GN reduce -> finalize -> GN+SiLU pack -> A2
    conv3x3_mma_k<16,128><<<dim3(64, 1, BB), 256, SMEM_128>>>(a1h, a1l, wh + WOFF1, wl + WOFF1,
                                                              x1, 128, red + 0*512, 2);
    finalize_k<<<1, 256>>>(red + 0*512, stats + 0*512, 4*HWP);
    gn_apply_pack_k<<<dim3(HWP/256, 8, BB), 256>>>(x1, off_g1, off_b1, stats + 0*512,
                                                   128, 0, 4, 0, a2h, a2l, 0, 8);

    // conv2 (128 -> 64) + fused GN reduce -> finalize -> GN+SiLU (fp32)
    conv3x3_mma_k<8,64><<<dim3(64, 1, BB), 256, SMEM_64>>>(a2h, a2l, wh + WOFF2, wl + WOFF2,
                                                           x2, 64, red + 1*512, 1);
    finalize_k<<<1, 256>>>(red + 1*512, stats + 1*512, 2*HWP);
    gn_apply_k<<<BB*64*HWP/256, 256>>>(x2, off_g2, off_b2, stats + 1*512, 64, 0, 64, 2, 0);

    // conv3 (64 -> 3) + bias
    conv3_k<<<dim3(64, 1, BB), 256>>>(x2, off_w3, off_bias3, pred);

    // warp -> aligned + flow (into d_out)
    warp_k<<<BB*HWP/256, 256>>>(feat2, pred, out);

    // cost volume (one pass)
    costvol_k<<<dim3(64, 1, BB), 256>>>(feat1, out + ALIGNED_OFF, cv);

    // corr/diff 1x1 + fused GN reduce
    conv1x1_k<81, 0><<<BB*HWP/128, 256>>>(cv, nullptr, corr_w, cd, 0, red + 2*512);
    conv1x1_k<128, 1><<<BB*HWP/128, 256>>>(feat1, out + ALIGNED_OFF, diff_w, cd, 64, red + 3*512);
    finalize_k<<<1, 256>>>(red + 2*512, stats + 2*512, 2*HWP);
    finalize_k<<<1, 256>>>(red + 3*512, stats + 3*512, 2*HWP);

    // GN + relu -> packed A3
    gn_apply_pack_k<<<dim3(HWP/256, 4, BB), 256>>>(cd, corr_g, corr_b, stats + 2*512,
                                                   128, 0, 2, 1, a3h, a3l, 0, 8);
    gn_apply_pack_k<<<dim3(HWP/256, 4, BB), 256>>>(cd, diff_g, diff_b, stats + 3*512,
                                                   128, 64, 2, 1, a3h, a3l, 4, 8);

    // fus1 (128 -> 128) + fused GN reduce; GN applied inside lam
    conv3x3_mma_k<8,128><<<dim3(64, 1, BB), 256, SMEM_128>>>(a3h, a3l, wh + WOFFF, wl + WOFFF,
                                                             f, 128, red + 4*512, 2);
    finalize_k<<<1, 256>>>(red + 4*512, stats + 4*512, 4*HWP);

    // fused fus2 + GN + relu + lam
    weff_k<<<1, 128>>>(fus_w2, lam_w, weff);
    lam_gn_k<<<BB*HWP/256, 256>>>(f, weff, fus_g1, fus_b1, stats + 4*512, lam_b, out);
}

// round 8
// speedup vs baseline: 1.0513x; 1.0513x over previous
#include <cuda_runtime.h>
#include <cuda_bf16.h>
#include <math.h>
#include <stdint.h>

#define BB 8
#define CCH 128
#define HH 128
#define WW 128
#define HWP (HH*WW)
#define RRAD 4

// ---------------- scratch (device globals; no allocation allowed) -------------
__device__ float g_x1[BB*CCH*HWP];     // conv1 out (fp32, pre-GN)
__device__ float g_x2[BB*64*HWP];      // conv2 out
__device__ float g_pred[BB*3*HWP];     // conv3 out (flow + validity logit)
__device__ float g_cv[BB*81*HWP];      // cost volume
__device__ float g_cd[BB*CCH*HWP];     // ce (ch 0-63) + de (ch 64-127), pre-GN
__device__ float g_f[BB*CCH*HWP];      // fus1 out (raw, pre-GN)
__device__ float g_weff[CCH];          // fused fus_w2 -> lam weight
__device__ float g_red[5*256*2];       // 5 GN sites x (B*32 groups) x (sum, sumsq)
__device__ float g_stats[5*256*2];     // 5 GN sites x (B*32 groups) x (mean, rstd)

// packed bf16 hi/lo activations: [b][ch16][y][x][c16]
__device__ __nv_bfloat16 g_a1h[(size_t)BB*16*HWP*16], g_a1l[(size_t)BB*16*HWP*16]; // conv1 in (256ch)
__device__ __nv_bfloat16 g_a2h[(size_t)BB*8*HWP*16],  g_a2l[(size_t)BB*8*HWP*16];  // conv2 in (128ch)
__device__ __nv_bfloat16 g_a3h[(size_t)BB*8*HWP*16],  g_a3l[(size_t)BB*8*HWP*16];  // fus1 in (128ch)

// bf16-split weights, pre-permuted: [cin_chunk][tap(9)][cout_all][cin16]
#define WOFF1 0
#define WOFF2 294912            // conv1: 128*256*9
#define WOFFF (294912 + 73728)  // conv2: 64*128*9
#define WTOT  (294912 + 73728 + 147456)
__device__ __nv_bfloat16 g_wh[WTOT];
__device__ __nv_bfloat16 g_wl[WTOT];

#define ALIGNED_OFF 0
#define FLOW_OFF (BB*CCH*HWP)
#define LAM_OFF  (FLOW_OFF + BB*2*HWP)

// ---------------- mma / cp.async helpers --------------------------------------
__device__ __forceinline__ void ldsm4(uint32_t& r0, uint32_t& r1, uint32_t& r2, uint32_t& r3,
                                      uint32_t addr) {
    asm volatile("ldmatrix.sync.aligned.m8n8.x4.shared.b16 {%0,%1,%2,%3},[%4];"
        : "=r"(r0), "=r"(r1), "=r"(r2), "=r"(r3) : "r"(addr));
}
__device__ __forceinline__ void mma16816(float* c, const uint32_t* a, const uint32_t* b) {
    asm volatile("mma.sync.aligned.m16n8k16.row.col.f32.bf16.bf16.f32 "
        "{%0,%1,%2,%3},{%4,%5,%6,%7},{%8,%9},{%0,%1,%2,%3};"
        : "+f"(c[0]), "+f"(c[1]), "+f"(c[2]), "+f"(c[3])
        : "r"(a[0]), "r"(a[1]), "r"(a[2]), "r"(a[3]), "r"(b[0]), "r"(b[1]));
}
__device__ __forceinline__ void cpasync16(uint32_t dst, const void* src) {
    asm volatile("cp.async.cg.shared.global [%0],[%1],16;" :: "r"(dst), "l"(src));
}
__device__ __forceinline__ void cpcommit() { asm volatile("cp.async.commit_group;"); }
template<int N> __device__ __forceinline__ void cpwait() {
    asm volatile("cp.async.wait_group %0;" :: "n"(N));
}

// ---------------- zero the reduction buffer -----------------------------------
__global__ void zero_red_k(float* __restrict__ red)
{
    int i = blockIdx.x*512 + threadIdx.x*2;
    red[i] = 0.f;
    red[i+1] = 0.f;
}

// ---------------- finalize: (sum, sumsq) -> (mean, rstd) ----------------------
__global__ void finalize_k(const float* __restrict__ red, float* __restrict__ stats, int N)
{
    int i = threadIdx.x;   // 256 = b*32+g
    float invN = 1.f / (float)N;
    float m = red[i*2] * invN;
    float var = red[i*2+1]*invN - m*m;
    stats[i*2]   = m;
    stats[i*2+1] = rsqrtf(fmaxf(var, 0.f) + 1e-5f);
}

// ---------------- weight prep: fp32 [COUT][CIN][9] -> split bf16 permuted -----
__global__ void wprep_k(const float* __restrict__ w, __nv_bfloat16* __restrict__ wh,
                        __nv_bfloat16* __restrict__ wl, int COUT, int CIN)
{
    int idx = blockIdx.x*256 + threadIdx.x;
    int total = COUT*CIN*9;
    if (idx >= total) return;
    int c16 = idx & 15;
    int co  = (idx >> 4) % COUT;
    int rest = (idx >> 4) / COUT;    // ch*9 + tap
    int tap = rest % 9;
    int ch = rest / 9;
    int cin = ch*16 + c16;
    float v = w[((size_t)co*CIN + cin)*9 + tap];
    __nv_bfloat16 h = __float2bfloat16(v);
    wh[idx] = h;
    wl[idx] = __float2bfloat16(v - __bfloat162float(h));
}

// ---------------- pack feat1+feat2 -> bf16 hi/lo packed (one launch) ----------
__global__ void pack2_k(const float* __restrict__ src1, const float* __restrict__ src2,
                        __nv_bfloat16* __restrict__ dh, __nv_bfloat16* __restrict__ dl)
{
    int p = blockIdx.x*256 + threadIdx.x;
    int by = blockIdx.y, b = blockIdx.z;          // by 0..15
    const float* src = (by < 8) ? src1 : src2;
    int cb = (by & 7)*16;
    union { uint4 u[2]; __nv_bfloat16 h[16]; } ph, pl;
    #pragma unroll
    for (int c = 0; c < 16; c++) {
        float v = src[((size_t)(b*128 + cb + c))*HWP + p];
        __nv_bfloat16 hh = __float2bfloat16(v);
        ph.h[c] = hh;
        pl.h[c] = __float2bfloat16(v - __bfloat162float(hh));
    }
    size_t e = (((size_t)(b*16 + by))*HWP + p)*16;
    ((uint4*)(dh + e))[0] = ph.u[0]; ((uint4*)(dh + e))[1] = ph.u[1];
    ((uint4*)(dl + e))[0] = pl.u[0]; ((uint4*)(dl + e))[1] = pl.u[1];
}

// ---------------- GN apply + act -> bf16 hi/lo packed -------------------------
__global__ void gn_apply_pack_k(const float* __restrict__ x, const float* __restrict__ gamma,
                                const float* __restrict__ beta, const float* __restrict__ stats,
                                int Ctot, int c_off_src, int cpg, int act,
                                __nv_bfloat16* __restrict__ dh, __nv_bfloat16* __restrict__ dl,
                                int ch_off, int NCHT)
{
    int p = blockIdx.x*256 + threadIdx.x;
    int by = blockIdx.y, b = blockIdx.z;
    union { uint4 u[2]; __nv_bfloat16 h[16]; } ph, pl;
    #pragma unroll
    for (int c = 0; c < 16; c++) {
        int cl = by*16 + c;
        int g = cl / cpg;
        float m = stats[(b*32 + g)*2];
        float r = stats[(b*32 + g)*2 + 1];
        float v = x[((size_t)(b*Ctot + c_off_src + cl))*HWP + p];
        v = (v - m) * r * gamma[cl] + beta[cl];
        if (act == 0) v = v / (1.f + expf(-v));
        else          v = fmaxf(v, 0.f);
        __nv_bfloat16 hh = __float2bfloat16(v);
        ph.h[c] = hh;
        pl.h[c] = __float2bfloat16(v - __bfloat162float(hh));
    }
    size_t e = (((size_t)(b*NCHT + ch_off + by))*HWP + p)*16;
    ((uint4*)(dh + e))[0] = ph.u[0]; ((uint4*)(dh + e))[1] = ph.u[1];
    ((uint4*)(dl + e))[0] = pl.u[0]; ((uint4*)(dl + e))[1] = pl.u[1];
}

// ---------------- tensor-core 3x3 conv, cp.async pipelined, fused GN-reduce ---
template<int NCH, int COUTB>
__global__ void __launch_bounds__(256)
conv3x3_mma_k(const __nv_bfloat16* __restrict__ aph, const __nv_bfloat16* __restrict__ apl,
              const __nv_bfloat16* __restrict__ gwh, const __nv_bfloat16* __restrict__ gwl,
              float* __restrict__ out, int COUT, float* __restrict__ red, int cpgshift)
{
    const int MF = COUTB/32;
    const int WPL = 9*COUTB*16;               // weight plane, elements
    const int WPLB = WPL*2;                   // weight plane, bytes
    const int WBUF = 2*WPLB;                  // one weight buffer (hi+lo), bytes
    const int APLB = 5440*2;                  // act plane bytes
    const int ABUF = 2*APLB;                  // one act buffer (hi+lo), bytes
    const int ABASE = 2*WBUF;
    extern __shared__ char dsm[];

    int b = blockIdx.z, tile = blockIdx.x;
    int X0 = (tile & 3) * 32;
    int Y0 = (tile >> 2) * 8;
    int tid = threadIdx.x;
    int wid = tid >> 5, lane = tid & 31;
    int cw = wid & 1, pw = wid >> 1;
    int g = lane >> 2, t = lane & 3;

    uint32_t sm_base = (uint32_t)__cvta_generic_to_shared(dsm);

    float acc[MF][8][4];
    #pragma unroll
    for (int mf = 0; mf < MF; mf++)
        #pragma unroll
        for (int j = 0; j < 8; j++)
            #pragma unroll
            for (int k = 0; k < 4; k++) acc[mf][j][k] = 0.f;

    int m = lane >> 3, ri = lane & 7;
    int a_kb = (m >> 1) * 8;
    int a_corow = (m & 1) * 8 + ri;
    uint32_t b_off[4];
    {
        int mm = lane >> 3;
        int rb = lane & 7;
        #pragma unroll
        for (int jp = 0; jp < 4; jp++) {
            int j = jp*2 + (mm >> 1);
            int kb = (mm & 1) * 8;
            int n = j*8 + rb;
            int rloc = n >> 5, xb = n & 31;
            b_off[jp] = (uint32_t)((((pw*2 + rloc)*34 + xb)*16 + kb) * 2);
        }
    }

    auto stage = [&](int ch, int bf) {
        const char* sh = (const char*)(gwh + (size_t)ch*WPL);
        const char* sl = (const char*)(gwl + (size_t)ch*WPL);
        uint32_t wd = sm_base + bf*WBUF;
        const int NV = WPLB/16;
        for (int i = tid; i < NV; i += 256) {
            cpasync16(wd + i*16, sh + i*16);
            cpasync16(wd + WPLB + i*16, sl + i*16);
        }
        uint32_t ad = sm_base + ABASE + bf*ABUF;
        uint4* dah = (uint4*)(dsm + ABASE + bf*ABUF);
        uint4* dal = (uint4*)(dsm + ABASE + bf*ABUF + APLB);
        const uint4 z = make_uint4(0,0,0,0);
        size_t basee = ((size_t)(b*NCH + ch))*HWP;
        for (int i = tid; i < 680; i += 256) {
            int pos = i >> 1, half = i & 1;
            int r = pos / 34, col = pos % 34;
            int gy = Y0 + r - 1, gx = X0 + col - 1;
            if (gy >= 0 && gy < HH && gx >= 0 && gx < WW) {
                size_t e = (basee + gy*WW + gx)*16 + half*8;
                cpasync16(ad + (pos*2 + half)*16, aph + e);
                cpasync16(ad + APLB + (pos*2 + half)*16, apl + e);
            } else {
                dah[pos*2 + half] = z;
                dal[pos*2 + half] = z;
            }
        }
    };

    stage(0, 0);
    cpcommit();

    for (int ch = 0; ch < NCH; ch++) {
        if (ch + 1 < NCH) { stage(ch + 1, (ch + 1) & 1); cpcommit(); cpwait<1>(); }
        else              { cpwait<0>(); }
        __syncthreads();

        int bf = ch & 1;
        uint32_t swb = sm_base + bf*WBUF;
        uint32_t sab = sm_base + ABASE + bf*ABUF;

        #pragma unroll
        for (int tap = 0; tap < 9; tap++) {
            int ky = tap / 3, kx = tap - ky*3;
            uint32_t ah[MF][4], al[MF][4];
            #pragma unroll
            for (int mf = 0; mf < MF; mf++) {
                uint32_t off = (uint32_t)(((tap*COUTB + cw*(COUTB/2) + mf*16 + a_corow)*16 + a_kb) * 2);
                ldsm4(ah[mf][0], ah[mf][1], ah[mf][2], ah[mf][3], swb + off);
                ldsm4(al[mf][0], al[mf][1], al[mf][2], al[mf][3], swb + (uint32_t)WPLB + off);
            }
            uint32_t tshift = (uint32_t)(((ky*34 + kx)*16) * 2);
            #pragma unroll
            for (int jp = 0; jp < 4; jp++) {
                uint32_t ba = sab + b_off[jp] + tshift;
                uint32_t bh[4], bl[4];
                ldsm4(bh[0], bh[1], bh[2], bh[3], ba);
                ldsm4(bl[0], bl[1], bl[2], bl[3], ba + (uint32_t)APLB);
                #pragma unroll
                for (int jj = 0; jj < 2; jj++) {
                    int j = jp*2 + jj;
                    #pragma unroll
                    for (int mf = 0; mf < MF; mf++) {
                        mma16816(acc[mf][j], ah[mf], &bh[jj*2]);
                        mma16816(acc[mf][j], ah[mf], &bl[jj*2]);
                        mma16816(acc[mf][j], al[mf], &bh[jj*2]);
                    }
                }
            }
        }
        __syncthreads();
    }

    // ---- fused GN partial reduction (sum, sumsq per group) ----
    {
        float* bins = (float*)dsm;    // 64 floats: 32 groups x (sum, sumsq)
        if (tid < 64) bins[tid] = 0.f;
        __syncthreads();
        #pragma unroll
        for (int mf = 0; mf < MF; mf++) {
            int cout0 = cw*(COUTB/2) + mf*16 + g;
            float s0 = 0.f, q0 = 0.f, s1 = 0.f, q1 = 0.f;
            #pragma unroll
            for (int j = 0; j < 8; j++) {
                s0 += acc[mf][j][0] + acc[mf][j][1];
                q0 += acc[mf][j][0]*acc[mf][j][0] + acc[mf][j][1]*acc[mf][j][1];
                s1 += acc[mf][j][2] + acc[mf][j][3];
                q1 += acc[mf][j][2]*acc[mf][j][2] + acc[mf][j][3]*acc[mf][j][3];
            }
            int g0 = cout0 >> cpgshift, g1 = (cout0 + 8) >> cpgshift;
            atomicAdd(&bins[g0*2],   s0);
            atomicAdd(&bins[g0*2+1], q0);
            atomicAdd(&bins[g1*2],   s1);
            atomicAdd(&bins[g1*2+1], q1);
        }
        __syncthreads();
        if (tid < 64) atomicAdd(&red[(b*32 + (tid>>1))*2 + (tid&1)], bins[tid]);
    }

    // ---- writeback ----
    #pragma unroll
    for (int mf = 0; mf < MF; mf++)
        #pragma unroll
        for (int j = 0; j < 8; j++) {
            int n0 = j*8 + 2*t;
            int rloc = n0 >> 5, x = n0 & 31;
            int py = Y0 + pw*2 + rloc, px = X0 + x;
            int cout0 = cw*(COUTB/2) + mf*16 + g;
            float2 v01 = make_float2(acc[mf][j][0], acc[mf][j][1]);
            float2 v23 = make_float2(acc[mf][j][2], acc[mf][j][3]);
            *(float2*)&out[((size_t)(b*COUT + cout0))*HWP + py*WW + px] = v01;
            *(float2*)&out[((size_t)(b*COUT + cout0 + 8))*HWP + py*WW + px] = v23;
        }
}

// ---------------- conv3: 64 -> 3, 3x3 pad=1, + bias ---------------------------
__global__ void conv3_k(const float* __restrict__ x, const float* __restrict__ w,
                        const float* __restrict__ bias, float* __restrict__ pred)
{
    const int CK = 8;
    __shared__ float s_in[CK][18][20];
    __shared__ float s_w[CK][9][4];
    int b = blockIdx.z;
    int X0 = (blockIdx.x & 7) * 16;
    int Y0 = (blockIdx.x >> 3) * 16;
    int tid = threadIdx.x;
    int ty = tid >> 4, tx = tid & 15;
    float acc[3] = {0.f, 0.f, 0.f};

    for (int c0 = 0; c0 < 64; c0 += CK) {
        for (int i = tid; i < CK*18*18; i += 256) {
            int c = i / 324, rem = i % 324, r = rem / 18, col = rem % 18;
            int gy = Y0 + r - 1, gx = X0 + col - 1;
            float v = 0.f;
            if (gy >= 0 && gy < HH && gx >= 0 && gx < WW)
                v = x[((size_t)(b*64 + c0 + c))*HWP + gy*WW + gx];
            s_in[c][r][col] = v;
        }
        for (int i = tid; i < CK*9*3; i += 256) {
            int c = i / 27, rem = i % 27, tap = rem / 3, o = rem % 3;
            s_w[c][tap][o] = w[(size_t)o*64*9 + (c0 + c)*9 + tap];
        }
        __syncthreads();
        #pragma unroll
        for (int c = 0; c < CK; c++)
            #pragma unroll
            for (int ky = 0; ky < 3; ky++)
                #pragma unroll
                for (int kx = 0; kx < 3; kx++) {
                    float v = s_in[c][ty + ky][tx + kx];
                    acc[0] += v * s_w[c][ky*3 + kx][0];
                    acc[1] += v * s_w[c][ky*3 + kx][1];
                    acc[2] += v * s_w[c][ky*3 + kx][2];
                }
        __syncthreads();
    }
    int p = (Y0 + ty)*WW + X0 + tx;
    pred[(size_t)(b*3 + 0)*HWP + p] = acc[0] + bias[0];
    pred[(size_t)(b*3 + 1)*HWP + p] = acc[1] + bias[1];
    pred[(size_t)(b*3 + 2)*HWP + p] = acc[2] + bias[2];
}

// ---------------- GroupNorm apply + act, fp32 in-place ------------------------
__global__ void gn_apply_k(float* __restrict__ x, const float* __restrict__ gamma,
                           const float* __restrict__ beta, const float* __restrict__ stats,
                           int Ctot, int c_off, int Csub, int cpg, int act)
{
    int idx = blockIdx.x*256 + threadIdx.x;
    int total = BB*Csub*HWP;
    if (idx >= total) return;
    int p = idx % HWP;
    int c = (idx / HWP) % Csub;
    int b = idx / (Csub*HWP);
    int g = c / cpg;
    float m = stats[(b*32 + g)*2];
    float r = stats[(b*32 + g)*2 + 1];
    size_t a = ((size_t)(b*Ctot + c_off + c))*HWP + p;
    float v = (x[a] - m) * r * gamma[c] + beta[c];
    if (act == 0) v = v / (1.f + expf(-v));
    else          v = fmaxf(v, 0.f);
    x[a] = v;
}

// ---------------- bilinear warp * validity; also writes flow ------------------
__global__ void warp_k(const float* __restrict__ feat2, const float* __restrict__ pred,
                       float* __restrict__ out)
{
    int idx = blockIdx.x*256 + threadIdx.x;
    int b = idx / HWP, p = idx % HWP;
    int yi = p / WW, xi = p % WW;
    float fx = pred[(size_t)(b*3 + 0)*HWP + p];
    float fy = pred[(size_t)(b*3 + 1)*HWP + p];
    float vl = pred[(size_t)(b*3 + 2)*HWP + p];
    float vald = 1.f / (1.f + expf(-vl));
    float px = xi + fx, py = yi + fy;
    float x0 = floorf(px), y0 = floorf(py);
    float wx = px - x0, wy = py - y0;

    float cx[2] = {x0, x0 + 1.f};
    float cy[2] = {y0, y0 + 1.f};
    float vxf[2], vyf[2];
    int xcl[2], ycl[2];
    #pragma unroll
    for (int k = 0; k < 2; k++) {
        vxf[k] = (cx[k] >= 0.f && cx[k] <= (float)(WW - 1)) ? 1.f : 0.f;
        vyf[k] = (cy[k] >= 0.f && cy[k] <= (float)(HH - 1)) ? 1.f : 0.f;
        int xv = (int)cx[k]; xv = xv < 0 ? 0 : (xv > WW-1 ? WW-1 : xv); xcl[k] = xv;
        int yv = (int)cy[k]; yv = yv < 0 ? 0 : (yv > HH-1 ? HH-1 : yv); ycl[k] = yv;
    }
    float wv[4];
    wv[0] = (1.f - wx)*(1.f - wy) * vxf[0]*vyf[0];
    wv[1] = wx*(1.f - wy)         * vxf[1]*vyf[0];
    wv[2] = (1.f - wx)*wy         * vxf[0]*vyf[1];
    wv[3] = wx*wy                 * vxf[1]*vyf[1];
    int off[4];
    off[0] = ycl[0]*WW + xcl[0];
    off[1] = ycl[0]*WW + xcl[1];
    off[2] = ycl[1]*WW + xcl[0];
    off[3] = ycl[1]*WW + xcl[1];

    const float* f2b = feat2 + (size_t)b*CCH*HWP;
    #pragma unroll 4
    for (int c = 0; c < CCH; c++) {
        const float* fc = f2b + (size_t)c*HWP;
        float v = wv[0]*fc[off[0]] + wv[1]*fc[off[1]] + wv[2]*fc[off[2]] + wv[3]*fc[off[3]];
        out[ALIGNED_OFF + ((size_t)(b*CCH + c))*HWP + p] = v * vald;
    }
    out[FLOW_OFF + (size_t)(b*2 + 0)*HWP + p] = fx;
    out[FLOW_OFF + (size_t)(b*2 + 1)*HWP + p] = fy;
}

// ---------------- cost volume: 3 dy-groups of 3, acc[27] ----------------------
__global__ void __launch_bounds__(256) costvol_k(const float* __restrict__ f1,
                                                 const float* __restrict__ al,
                                                 float* __restrict__ cv)
{
    const int CK = 4;
    __shared__ float s_f1[CK][16][16];
    __shared__ float s_al[CK][18][24];
    int b = blockIdx.z;
    int dyg = blockIdx.y;                  // 0..2 -> dy in {3*dyg, 3*dyg+1, 3*dyg+2}
    int tile = blockIdx.x;
    int X0 = (tile & 7) * 16;
    int Y0 = (tile >> 3) * 16;
    int tid = threadIdx.x;
    int ty = tid >> 4, tx = tid & 15;
    float acc[27];
    #pragma unroll
    for (int d = 0; d < 27; d++) acc[d] = 0.f;

    int dy0 = dyg*3;
    for (int c0 = 0; c0 < CCH; c0 += CK) {
        for (int i = tid; i < CK*256; i += 256) {
            int c = i >> 8, r = (i >> 4) & 15, col = i & 15;
            s_f1[c][r][col] = f1[((size_t)(b*CCH + c0 + c))*HWP + (Y0 + r)*WW + X0 + col];
        }
        for (int i = tid; i < CK*432; i += 256) {
            int c = i / 432, rem = i % 432, r = rem / 24, col = rem % 24;
            int gy = Y0 + r + dy0 - RRAD;
            int gx = X0 + col - RRAD;
            float v = 0.f;
            if (gy >= 0 && gy < HH && gx >= 0 && gx < WW)
                v = al[((size_t)(b*CCH + c0 + c))*HWP + gy*WW + gx];
            s_al[c][r][col] = v;
        }
        __syncthreads();
        #pragma unroll
        for (int c = 0; c < CK; c++) {
            float f = s_f1[c][ty][tx];
            #pragma unroll
            for (int dyi = 0; dyi < 3; dyi++)
                #pragma unroll
                for (int dx = 0; dx < 9; dx++)
                    acc[dyi*9 + dx] += f * s_al[c][ty + dyi][tx + dx];
        }
        __syncthreads();
    }
    int p = (Y0 + ty)*WW + X0 + tx;
    #pragma unroll
    for (int dyi = 0; dyi < 3; dyi++)
        #pragma unroll
        for (int dx = 0; dx < 9; dx++)
            cv[((size_t)(b*81 + (dy0 + dyi)*9 + dx))*HWP + p] = acc[dyi*9 + dx] * (1.0f/CCH);
}

// ---------------- 1x1 conv + fused GN reduce (MODE 0 plain, 1 |A-B|) ----------
template<int CIN, int MODE>
__global__ void conv1x1_k(const float* __restrict__ inA, const float* __restrict__ inB,
                          const float* __restrict__ wgt, float* __restrict__ out, int c_off,
                          float* __restrict__ red)
{
    const int CK = 8;
    __shared__ float s_w[CK][64];
    __shared__ float s_x[CK][128];
    __shared__ float bins[64];
    int tid = threadIdx.x;
    int P0 = blockIdx.x * 128;
    int b = P0 / HWP;
    int p0 = P0 % HWP;
    int co_g = tid >> 5;
    int pg = tid & 31;
    float acc[8][4];
    #pragma unroll
    for (int k = 0; k < 8; k++)
        #pragma unroll
        for (int j = 0; j < 4; j++) acc[k][j] = 0.f;
    if (tid < 64) bins[tid] = 0.f;

    for (int c0 = 0; c0 < CIN; c0 += CK) {
        for (int i = tid; i < CK*64; i += 256) {
            int c = i >> 6, o = i & 63;
            int ci = c0 + c;
            s_w[c][o] = (ci < CIN) ? wgt[(size_t)o*CIN + ci] : 0.f;
        }
        for (int i = tid; i < CK*128; i += 256) {
            int c = i >> 7, px = i & 127;
            int ci = c0 + c;
            float v = 0.f;
            if (ci < CIN) {
                if (MODE == 0) {
                    v = inA[((size_t)(b*CIN + ci))*HWP + p0 + px];
                } else {
                    size_t gi = ((size_t)(b*CCH + ci))*HWP + p0 + px;
                    v = fabsf(inA[gi] - inB[gi]);
                }
            }
            s_x[c][px] = v;
        }
        __syncthreads();
        #pragma unroll
        for (int c = 0; c < CK; c++) {
            float4 wa = *(const float4*)&s_w[c][co_g*8];
            float4 wb = *(const float4*)&s_w[c][co_g*8 + 4];
            float4 x4 = *(const float4*)&s_x[c][pg*4];
            float w8[8] = {wa.x, wa.y, wa.z, wa.w, wb.x, wb.y, wb.z, wb.w};
            float xv[4] = {x4.x, x4.y, x4.z, x4.w};
            #pragma unroll
            for (int k = 0; k < 8; k++)
                #pragma unroll
                for (int j = 0; j < 4; j++) acc[k][j] += w8[k]*xv[j];
        }
        __syncthreads();
    }
    #pragma unroll
    for (int k = 0; k < 8; k++) {
        int cl = co_g*8 + k;
        float s = acc[k][0]+acc[k][1]+acc[k][2]+acc[k][3];
        float q = acc[k][0]*acc[k][0]+acc[k][1]*acc[k][1]+acc[k][2]*acc[k][2]+acc[k][3]*acc[k][3];
        atomicAdd(&bins[(cl>>1)*2],   s);
        atomicAdd(&bins[(cl>>1)*2+1], q);
        int oc = c_off + cl;
        float4 r4 = make_float4(acc[k][0], acc[k][1], acc[k][2], acc[k][3]);
        *(float4*)&out[((size_t)(b*CCH + oc))*HWP + p0 + pg*4] = r4;
    }
    __syncthreads();
    if (tid < 64) atomicAdd(&red[(b*32 + (tid>>1))*2 + (tid&1)], bins[tid]);
}

// ---------------- fused fus_w2 -> lam weight ----------------------------------
__global__ void weff_k(const float* __restrict__ fus_w2, const float* __restrict__ lam_w,
                       float* __restrict__ weff)
{
    int c = threadIdx.x;
    float s = 0.f;
    for (int o = 0; o < 128; o++) s += lam_w[o] * fus_w2[(size_t)o*128 + c];
    weff[c] = s;
}

// ---------------- lam = sigmoid(dot(weff, relu(GN(f))) + lam_b) ---------------
__global__ void lam_gn_k(const float* __restrict__ f, const float* __restrict__ weff,
                         const float* __restrict__ gamma, const float* __restrict__ beta,
                         const float* __restrict__ stats, const float* __restrict__ lam_b,
                         float* __restrict__ out)
{
    __shared__ float sw[128], sa[128], sb[128];
    int tid = threadIdx.x;
    int idx = blockIdx.x*256 + tid;
    int b = idx / HWP, p = idx % HWP;
    if (tid < 128) {
        int c = tid;
        float mm = stats[(b*32 + c/4)*2];
        float rr = stats[(b*32 + c/4)*2 + 1];
        float ga = gamma[c]*rr;
        sw[c] = weff[c];
        sa[c] = ga;
        sb[c] = beta[c] - mm*ga;
    }
    __syncthreads();
    float s = lam_b[0];
    const float* fb = f + (size_t)b*CCH*HWP + p;
    #pragma unroll 4
    for (int c = 0; c < CCH; c++) {
        float v = fmaxf(fmaf(fb[(size_t)c*HWP], sa[c], sb[c]), 0.f);
        s = fmaf(sw[c], v, s);
    }
    out[LAM_OFF + idx] = 1.f / (1.f + expf(-s));
}

// ---------------- launch ------------------------------------------------------
extern "C" void kernel_launch(void* const* d_in, const int* in_sizes, int n_in,
                              void* d_out, int out_size)
{
    const float* feat1    = (const float*)d_in[0];
    const float* feat2    = (const float*)d_in[1];
    const float* off_w1   = (const float*)d_in[2];
    const float* off_g1   = (const float*)d_in[3];
    const float* off_b1   = (const float*)d_in[4];
    const float* off_w2   = (const float*)d_in[5];
    const float* off_g2   = (const float*)d_in[6];
    const float* off_b2   = (const float*)d_in[7];
    const float* off_w3   = (const float*)d_in[8];
    const float* off_bias3= (const float*)d_in[9];
    const float* corr_w   = (const float*)d_in[10];
    const float* corr_g   = (const float*)d_in[11];
    const float* corr_b   = (const float*)d_in[12];
    const float* diff_w   = (const float*)d_in[13];
    const float* diff_g   = (const float*)d_in[14];
    const float* diff_b   = (const float*)d_in[15];
    const float* fus_w1   = (const float*)d_in[16];
    const float* fus_g1   = (const float*)d_in[17];
    const float* fus_b1   = (const float*)d_in[18];
    const float* fus_w2   = (const float*)d_in[19];
    const float* lam_w    = (const float*)d_in[20];
    const float* lam_b    = (const float*)d_in[21];
    float* out = (float*)d_out;

    float *x1, *x2, *pred, *cv, *cd, *f, *weff, *red, *stats;
    __nv_bfloat16 *wh, *wl, *a1h, *a1l, *a2h, *a2l, *a3h, *a3l;
    cudaGetSymbolAddress((void**)&x1,   g_x1);
    cudaGetSymbolAddress((void**)&x2,   g_x2);
    cudaGetSymbolAddress((void**)&pred, g_pred);
    cudaGetSymbolAddress((void**)&cv,   g_cv);
    cudaGetSymbolAddress((void**)&cd,   g_cd);
    cudaGetSymbolAddress((void**)&f,    g_f);
    cudaGetSymbolAddress((void**)&weff, g_weff);
    cudaGetSymbolAddress((void**)&red,  g_red);
    cudaGetSymbolAddress((void**)&stats,g_stats);
    cudaGetSymbolAddress((void**)&wh,   g_wh);
    cudaGetSymbolAddress((void**)&wl,   g_wl);
    cudaGetSymbolAddress((void**)&a1h,  g_a1h);
    cudaGetSymbolAddress((void**)&a1l,  g_a1l);
    cudaGetSymbolAddress((void**)&a2h,  g_a2h);
    cudaGetSymbolAddress((void**)&a2l,  g_a2l);
    cudaGetSymbolAddress((void**)&a3h,  g_a3h);
    cudaGetSymbolAddress((void**)&a3l,  g_a3l);

    const int SMEM_128 = 2*(2*9*128*16*2) + 2*(2*5440*2);   // 190976
    const int SMEM_64  = 2*(2*9*64*16*2)  + 2*(2*5440*2);   // 117248
    cudaFuncSetAttribute(conv3x3_mma_k<16,128>, cudaFuncAttributeMaxDynamicSharedMemorySize, SMEM_128);
    cudaFuncSetAttribute(conv3x3_mma_k<8,128>,  cudaFuncAttributeMaxDynamicSharedMemorySize, SMEM_128);
    cudaFuncSetAttribute(conv3x3_mma_k<8,64>,   cudaFuncAttributeMaxDynamicSharedMemorySize, SMEM_64);

    // zero GN reduction buffer
    zero_red_k<<<5, 256>>>(red);

    // weight prep
    wprep_k<<<(128*256*9 + 255)/256, 256>>>(off_w1, wh + WOFF1, wl + WOFF1, 128, 256);
    wprep_k<<<( 64*128*9 + 255)/256, 256>>>(off_w2, wh + WOFF2, wl + WOFF2,  64, 128);
    wprep_k<<<(128*128*9 + 255)/256, 256>>>(fus_w1, wh + WOFFF, wl + WOFFF, 128, 128);

    // pack conv1 inputs (feat1 -> groups 0..7, feat2 -> 8..15), one launch
    pack2_k<<<dim3(HWP/256, 16, BB), 256>>>(feat1, feat2, a1h, a1l);

    // conv1 (256 -> 128) + fused GN reduce -> finalize -> GN+SiLU pack -> A2
    conv3x3_mma_k<16,128><<<dim3(64, 1, BB), 256, SMEM_128>>>(a1h, a1l, wh + WOFF1, wl + WOFF1,
                                                              x1, 128, red + 0*512, 2);
    finalize_k<<<1, 256>>>(red + 0*512, stats + 0*512, 4*HWP);
    gn_apply_pack_k<<<dim3(HWP/256, 8, BB), 256>>>(x1, off_g1, off_b1, stats + 0*512,
                                                   128, 0, 4, 0, a2h, a2l, 0, 8);

    // conv2 (128 -> 64) + fused GN reduce -> finalize -> GN+SiLU (fp32)
    conv3x3_mma_k<8,64><<<dim3(64, 1, BB), 256, SMEM_64>>>(a2h, a2l, wh + WOFF2, wl + WOFF2,
                                                           x2, 64, red + 1*512, 1);
    finalize_k<<<1, 256>>>(red + 1*512, stats + 1*512, 2*HWP);
    gn_apply_k<<<BB*64*HWP/256, 256>>>(x2, off_g2, off_b2, stats + 1*512, 64, 0, 64, 2, 0);

    // conv3 (64 -> 3) + bias
    conv3_k<<<dim3(64, 1, BB), 256>>>(x2, off_w3, off_bias3, pred);

    // warp -> aligned + flow (into d_out)
    warp_k<<<BB*HWP/256, 256>>>(feat2, pred, out);

    // cost volume (3 dy-groups)
    costvol_k<<<dim3(64, 3, BB), 256>>>(feat1, out + ALIGNED_OFF, cv);

    // corr/diff 1x1 + fused GN reduce
    conv1x1_k<81, 0><<<BB*HWP/128, 256>>>(cv, nullptr, corr_w, cd, 0, red + 2*512);
    conv1x1_k<128, 1><<<BB*HWP/128, 256>>>(feat1, out + ALIGNED_OFF, diff_w, cd, 64, red + 3*512);
    finalize_k<<<1, 256>>>(red + 2*512, stats + 2*512, 2*HWP);
    finalize_k<<<1, 256>>>(red + 3*512, stats + 3*512, 2*HWP);

    // GN + relu -> packed A3
    gn_apply_pack_k<<<dim3(HWP/256, 4, BB), 256>>>(cd, corr_g, corr_b, stats + 2*512,
                                                   128, 0, 2, 1, a3h, a3l, 0, 8);
    gn_apply_pack_k<<<dim3(HWP/256, 4, BB), 256>>>(cd, diff_g, diff_b, stats + 3*512,
                                                   128, 64, 2, 1, a3h, a3l, 4, 8);

    // fus1 (128 -> 128) + fused GN reduce; GN applied inside lam
    conv3x3_mma_k<8,128><<<dim3(64, 1, BB), 256, SMEM_128>>>(a3h, a3l, wh + WOFFF, wl + WOFFF,
                                                             f, 128, red + 4*512, 2);
    finalize_k<<<1, 256>>>(red + 4*512, stats + 4*512, 4*HWP);

    // fused fus2 + GN + relu + lam
    weff_k<<<1, 128>>>(fus_w2, lam_w, weff);
    lam_gn_k<<<BB*HWP/256, 256>>>(f, weff, fus_g1, fus_b1, stats + 4*512, lam_b, out);
}

// round 10
// speedup vs baseline: 1.2487x; 1.1877x over previous
#include <cuda_runtime.h>
#include <cuda_bf16.h>
#include <math.h>
#include <stdint.h>

#define BB 8
#define CCH 128
#define HH 128
#define WW 128
#define HWP (HH*WW)
#define RRAD 4

// ---------------- scratch (device globals; no allocation allowed) -------------
__device__ float g_x1[BB*CCH*HWP];     // conv1 out (fp32, pre-GN)
__device__ float g_x2[BB*64*HWP];      // conv2 out
__device__ float g_pred[BB*3*HWP];     // conv3 out (flow + validity logit)
__device__ float g_cv[BB*81*HWP];      // cost volume
__device__ float g_cd[BB*CCH*HWP];     // ce (ch 0-63) + de (ch 64-127), pre-GN
__device__ float g_f[BB*CCH*HWP];      // fus1 out (raw, pre-GN)
__device__ float g_weff[CCH];          // fused fus_w2 -> lam weight
__device__ float g_stats[5*256*2];     // 5 GN sites x (B*32 groups) x (mean, rstd)

// packed bf16 hi/lo activations: [b][ch16][y][x][c16]
__device__ __nv_bfloat16 g_a1h[(size_t)BB*16*HWP*16], g_a1l[(size_t)BB*16*HWP*16]; // conv1 in (256ch)
__device__ __nv_bfloat16 g_a2h[(size_t)BB*8*HWP*16],  g_a2l[(size_t)BB*8*HWP*16];  // conv2 in (128ch)
__device__ __nv_bfloat16 g_a3h[(size_t)BB*8*HWP*16],  g_a3l[(size_t)BB*8*HWP*16];  // fus1 in (128ch)

// bf16-split weights, pre-permuted: [cin_chunk][tap(9)][cout_all][cin16]
#define WOFF1 0
#define WOFF2 294912            // conv1: 128*256*9
#define WOFFF (294912 + 73728)  // conv2: 64*128*9
#define WTOT  (294912 + 73728 + 147456)
__device__ __nv_bfloat16 g_wh[WTOT];
__device__ __nv_bfloat16 g_wl[WTOT];

#define ALIGNED_OFF 0
#define FLOW_OFF (BB*CCH*HWP)
#define LAM_OFF  (FLOW_OFF + BB*2*HWP)

// ---------------- mma / cp.async helpers --------------------------------------
__device__ __forceinline__ void ldsm4(uint32_t& r0, uint32_t& r1, uint32_t& r2, uint32_t& r3,
                                      uint32_t addr) {
    asm volatile("ldmatrix.sync.aligned.m8n8.x4.shared.b16 {%0,%1,%2,%3},[%4];"
        : "=r"(r0), "=r"(r1), "=r"(r2), "=r"(r3) : "r"(addr));
}
__device__ __forceinline__ void mma16816(float* c, const uint32_t* a, const uint32_t* b) {
    asm volatile("mma.sync.aligned.m16n8k16.row.col.f32.bf16.bf16.f32 "
        "{%0,%1,%2,%3},{%4,%5,%6,%7},{%8,%9},{%0,%1,%2,%3};"
        : "+f"(c[0]), "+f"(c[1]), "+f"(c[2]), "+f"(c[3])
        : "r"(a[0]), "r"(a[1]), "r"(a[2]), "r"(a[3]), "r"(b[0]), "r"(b[1]));
}
__device__ __forceinline__ void cpasync16(uint32_t dst, const void* src) {
    asm volatile("cp.async.cg.shared.global [%0],[%1],16;" :: "r"(dst), "l"(src));
}
__device__ __forceinline__ void cpcommit() { asm volatile("cp.async.commit_group;"); }
template<int N> __device__ __forceinline__ void cpwait() {
    asm volatile("cp.async.wait_group %0;" :: "n"(N));
}

// ---------------- weight prep: fp32 [COUT][CIN][9] -> split bf16 permuted -----
__global__ void wprep_k(const float* __restrict__ w, __nv_bfloat16* __restrict__ wh,
                        __nv_bfloat16* __restrict__ wl, int COUT, int CIN)
{
    int idx = blockIdx.x*256 + threadIdx.x;
    int total = COUT*CIN*9;
    if (idx >= total) return;
    int c16 = idx & 15;
    int co  = (idx >> 4) % COUT;
    int rest = (idx >> 4) / COUT;    // ch*9 + tap
    int tap = rest % 9;
    int ch = rest / 9;
    int cin = ch*16 + c16;
    float v = w[((size_t)co*CIN + cin)*9 + tap];
    __nv_bfloat16 h = __float2bfloat16(v);
    wh[idx] = h;
    wl[idx] = __float2bfloat16(v - __bfloat162float(h));
}

// ---------------- pack feat1+feat2 -> bf16 hi/lo packed (one launch) ----------
__global__ void pack2_k(const float* __restrict__ src1, const float* __restrict__ src2,
                        __nv_bfloat16* __restrict__ dh, __nv_bfloat16* __restrict__ dl)
{
    int p = blockIdx.x*256 + threadIdx.x;
    int by = blockIdx.y, b = blockIdx.z;          // by 0..15
    const float* src = (by < 8) ? src1 : src2;
    int cb = (by & 7)*16;
    union { uint4 u[2]; __nv_bfloat16 h[16]; } ph, pl;
    #pragma unroll
    for (int c = 0; c < 16; c++) {
        float v = src[((size_t)(b*128 + cb + c))*HWP + p];
        __nv_bfloat16 hh = __float2bfloat16(v);
        ph.h[c] = hh;
        pl.h[c] = __float2bfloat16(v - __bfloat162float(hh));
    }
    size_t e = (((size_t)(b*16 + by))*HWP + p)*16;
    ((uint4*)(dh + e))[0] = ph.u[0]; ((uint4*)(dh + e))[1] = ph.u[1];
    ((uint4*)(dl + e))[0] = pl.u[0]; ((uint4*)(dl + e))[1] = pl.u[1];
}

// ---------------- GN apply + act -> bf16 hi/lo packed -------------------------
__global__ void gn_apply_pack_k(const float* __restrict__ x, const float* __restrict__ gamma,
                                const float* __restrict__ beta, const float* __restrict__ stats,
                                int Ctot, int c_off_src, int cpg, int act,
                                __nv_bfloat16* __restrict__ dh, __nv_bfloat16* __restrict__ dl,
                                int ch_off, int NCHT)
{
    int p = blockIdx.x*256 + threadIdx.x;
    int by = blockIdx.y, b = blockIdx.z;
    union { uint4 u[2]; __nv_bfloat16 h[16]; } ph, pl;
    #pragma unroll
    for (int c = 0; c < 16; c++) {
        int cl = by*16 + c;
        int g = cl / cpg;
        float m = stats[(b*32 + g)*2];
        float r = stats[(b*32 + g)*2 + 1];
        float v = x[((size_t)(b*Ctot + c_off_src + cl))*HWP + p];
        v = (v - m) * r * gamma[cl] + beta[cl];
        if (act == 0) v = v / (1.f + expf(-v));
        else          v = fmaxf(v, 0.f);
        __nv_bfloat16 hh = __float2bfloat16(v);
        ph.h[c] = hh;
        pl.h[c] = __float2bfloat16(v - __bfloat162float(hh));
    }
    size_t e = (((size_t)(b*NCHT + ch_off + by))*HWP + p)*16;
    ((uint4*)(dh + e))[0] = ph.u[0]; ((uint4*)(dh + e))[1] = ph.u[1];
    ((uint4*)(dl + e))[0] = pl.u[0]; ((uint4*)(dl + e))[1] = pl.u[1];
}

// ---------------- tensor-core 3x3 conv, pad=1, cp.async double-buffered -------
template<int NCH, int COUTB>
__global__ void __launch_bounds__(256)
conv3x3_mma_k(const __nv_bfloat16* __restrict__ aph, const __nv_bfloat16* __restrict__ apl,
              const __nv_bfloat16* __restrict__ gwh, const __nv_bfloat16* __restrict__ gwl,
              float* __restrict__ out, int COUT)
{
    const int MF = COUTB/32;
    const int WPL = 9*COUTB*16;               // weight plane, elements
    const int WPLB = WPL*2;                   // weight plane, bytes
    const int WBUF = 2*WPLB;                  // one weight buffer (hi+lo), bytes
    const int APLB = 5440*2;                  // act plane bytes
    const int ABUF = 2*APLB;                  // one act buffer (hi+lo), bytes
    const int ABASE = 2*WBUF;
    extern __shared__ char dsm[];

    int b = blockIdx.z, tile = blockIdx.x;
    int X0 = (tile & 3) * 32;
    int Y0 = (tile >> 2) * 8;
    int tid = threadIdx.x;
    int wid = tid >> 5, lane = tid & 31;
    int cw = wid & 1, pw = wid >> 1;
    int g = lane >> 2, t = lane & 3;

    uint32_t sm_base = (uint32_t)__cvta_generic_to_shared(dsm);

    float acc[MF][8][4];
    #pragma unroll
    for (int mf = 0; mf < MF; mf++)
        #pragma unroll
        for (int j = 0; j < 8; j++)
            #pragma unroll
            for (int k = 0; k < 4; k++) acc[mf][j][k] = 0.f;

    int m = lane >> 3, ri = lane & 7;
    int a_kb = (m >> 1) * 8;
    int a_corow = (m & 1) * 8 + ri;
    uint32_t b_off[4];
    {
        int mm = lane >> 3;
        int rb = lane & 7;
        #pragma unroll
        for (int jp = 0; jp < 4; jp++) {
            int j = jp*2 + (mm >> 1);
            int kb = (mm & 1) * 8;
            int n = j*8 + rb;
            int rloc = n >> 5, xb = n & 31;
            b_off[jp] = (uint32_t)((((pw*2 + rloc)*34 + xb)*16 + kb) * 2);
        }
    }

    auto stage = [&](int ch, int bf) {
        const char* sh = (const char*)(gwh + (size_t)ch*WPL);
        const char* sl = (const char*)(gwl + (size_t)ch*WPL);
        uint32_t wd = sm_base + bf*WBUF;
        const int NV = WPLB/16;
        for (int i = tid; i < NV; i += 256) {
            cpasync16(wd + i*16, sh + i*16);
            cpasync16(wd + WPLB + i*16, sl + i*16);
        }
        uint32_t ad = sm_base + ABASE + bf*ABUF;
        uint4* dah = (uint4*)(dsm + ABASE + bf*ABUF);
        uint4* dal = (uint4*)(dsm + ABASE + bf*ABUF + APLB);
        const uint4 z = make_uint4(0,0,0,0);
        size_t basee = ((size_t)(b*NCH + ch))*HWP;
        for (int i = tid; i < 680; i += 256) {
            int pos = i >> 1, half = i & 1;
            int r = pos / 34, col = pos % 34;
            int gy = Y0 + r - 1, gx = X0 + col - 1;
            if (gy >= 0 && gy < HH && gx >= 0 && gx < WW) {
                size_t e = (basee + gy*WW + gx)*16 + half*8;
                cpasync16(ad + (pos*2 + half)*16, aph + e);
                cpasync16(ad + APLB + (pos*2 + half)*16, apl + e);
            } else {
                dah[pos*2 + half] = z;
                dal[pos*2 + half] = z;
            }
        }
    };

    stage(0, 0);
    cpcommit();

    for (int ch = 0; ch < NCH; ch++) {
        if (ch + 1 < NCH) { stage(ch + 1, (ch + 1) & 1); cpcommit(); cpwait<1>(); }
        else              { cpwait<0>(); }
        __syncthreads();

        int bf = ch & 1;
        uint32_t swb = sm_base + bf*WBUF;
        uint32_t sab = sm_base + ABASE + bf*ABUF;

        #pragma unroll
        for (int tap = 0; tap < 9; tap++) {
            int ky = tap / 3, kx = tap - ky*3;
            uint32_t ah[MF][4], al[MF][4];
            #pragma unroll
            for (int mf = 0; mf < MF; mf++) {
                uint32_t off = (uint32_t)(((tap*COUTB + cw*(COUTB/2) + mf*16 + a_corow)*16 + a_kb) * 2);
                ldsm4(ah[mf][0], ah[mf][1], ah[mf][2], ah[mf][3], swb + off);
                ldsm4(al[mf][0], al[mf][1], al[mf][2], al[mf][3], swb + (uint32_t)WPLB + off);
            }
            uint32_t tshift = (uint32_t)(((ky*34 + kx)*16) * 2);
            #pragma unroll
            for (int jp = 0; jp < 4; jp++) {
                uint32_t ba = sab + b_off[jp] + tshift;
                uint32_t bh[4], bl[4];
                ldsm4(bh[0], bh[1], bh[2], bh[3], ba);
                ldsm4(bl[0], bl[1], bl[2], bl[3], ba + (uint32_t)APLB);
                #pragma unroll
                for (int jj = 0; jj < 2; jj++) {
                    int j = jp*2 + jj;
                    #pragma unroll
                    for (int mf = 0; mf < MF; mf++) {
                        mma16816(acc[mf][j], ah[mf], &bh[jj*2]);
                        mma16816(acc[mf][j], ah[mf], &bl[jj*2]);
                        mma16816(acc[mf][j], al[mf], &bh[jj*2]);
                    }
                }
            }
        }
        __syncthreads();
    }

    // ---- writeback ----
    #pragma unroll
    for (int mf = 0; mf < MF; mf++)
        #pragma unroll
        for (int j = 0; j < 8; j++) {
            int n0 = j*8 + 2*t;
            int rloc = n0 >> 5, x = n0 & 31;
            int py = Y0 + pw*2 + rloc, px = X0 + x;
            int cout0 = cw*(COUTB/2) + mf*16 + g;
            float2 v01 = make_float2(acc[mf][j][0], acc[mf][j][1]);
            float2 v23 = make_float2(acc[mf][j][2], acc[mf][j][3]);
            *(float2*)&out[((size_t)(b*COUT + cout0))*HWP + py*WW + px] = v01;
            *(float2*)&out[((size_t)(b*COUT + cout0 + 8))*HWP + py*WW + px] = v23;
        }
}

// ---------------- conv3: 64 -> 3, 3x3 pad=1, + bias ---------------------------
__global__ void conv3_k(const float* __restrict__ x, const float* __restrict__ w,
                        const float* __restrict__ bias, float* __restrict__ pred)
{
    const int CK = 8;
    __shared__ float s_in[CK][18][20];
    __shared__ float s_w[CK][9][4];
    int b = blockIdx.z;
    int X0 = (blockIdx.x & 7) * 16;
    int Y0 = (blockIdx.x >> 3) * 16;
    int tid = threadIdx.x;
    int ty = tid >> 4, tx = tid & 15;
    float acc[3] = {0.f, 0.f, 0.f};

    for (int c0 = 0; c0 < 64; c0 += CK) {
        for (int i = tid; i < CK*18*18; i += 256) {
            int c = i / 324, rem = i % 324, r = rem / 18, col = rem % 18;
            int gy = Y0 + r - 1, gx = X0 + col - 1;
            float v = 0.f;
            if (gy >= 0 && gy < HH && gx >= 0 && gx < WW)
                v = x[((size_t)(b*64 + c0 + c))*HWP + gy*WW + gx];
            s_in[c][r][col] = v;
        }
        for (int i = tid; i < CK*9*3; i += 256) {
            int c = i / 27, rem = i % 27, tap = rem / 3, o = rem % 3;
            s_w[c][tap][o] = w[(size_t)o*64*9 + (c0 + c)*9 + tap];
        }
        __syncthreads();
        #pragma unroll
        for (int c = 0; c < CK; c++)
            #pragma unroll
            for (int ky = 0; ky < 3; ky++)
                #pragma unroll
                for (int kx = 0; kx < 3; kx++) {
                    float v = s_in[c][ty + ky][tx + kx];
                    acc[0] += v * s_w[c][ky*3 + kx][0];
                    acc[1] += v * s_w[c][ky*3 + kx][1];
                    acc[2] += v * s_w[c][ky*3 + kx][2];
                }
        __syncthreads();
    }
    int p = (Y0 + ty)*WW + X0 + tx;
    pred[(size_t)(b*3 + 0)*HWP + p] = acc[0] + bias[0];
    pred[(size_t)(b*3 + 1)*HWP + p] = acc[1] + bias[1];
    pred[(size_t)(b*3 + 2)*HWP + p] = acc[2] + bias[2];
}

// ---------------- GroupNorm stats (mean, rstd) --------------------------------
__global__ void gn_stats_k(const float* __restrict__ x, int Ctot, int c_off, int cpg,
                           float* __restrict__ stats)
{
    int bg = blockIdx.x;
    int b = bg >> 5, g = bg & 31;
    int tid = threadIdx.x;
    int N = cpg * HWP;
    const float* base = x + ((size_t)(b*Ctot + c_off + g*cpg))*HWP;
    float s = 0.f, s2 = 0.f;
    for (int i = tid; i < N; i += 256) {
        float v = base[i];
        s += v; s2 += v*v;
    }
    __shared__ float rs[256], rs2[256];
    rs[tid] = s; rs2[tid] = s2;
    __syncthreads();
    for (int st = 128; st > 0; st >>= 1) {
        if (tid < st) { rs[tid] += rs[tid + st]; rs2[tid] += rs2[tid + st]; }
        __syncthreads();
    }
    if (tid == 0) {
        float m = rs[0] / N;
        float var = rs2[0] / N - m*m;
        stats[bg*2]     = m;
        stats[bg*2 + 1] = rsqrtf(fmaxf(var, 0.f) + 1e-5f);
    }
}

// ---------------- GroupNorm apply + act, fp32 in-place ------------------------
__global__ void gn_apply_k(float* __restrict__ x, const float* __restrict__ gamma,
                           const float* __restrict__ beta, const float* __restrict__ stats,
                           int Ctot, int c_off, int Csub, int cpg, int act)
{
    int idx = blockIdx.x*256 + threadIdx.x;
    int total = BB*Csub*HWP;
    if (idx >= total) return;
    int p = idx % HWP;
    int c = (idx / HWP) % Csub;
    int b = idx / (Csub*HWP);
    int g = c / cpg;
    float m = stats[(b*32 + g)*2];
    float r = stats[(b*32 + g)*2 + 1];
    size_t a = ((size_t)(b*Ctot + c_off + c))*HWP + p;
    float v = (x[a] - m) * r * gamma[c] + beta[c];
    if (act == 0) v = v / (1.f + expf(-v));
    else          v = fmaxf(v, 0.f);
    x[a] = v;
}

// ---------------- bilinear warp * validity; also writes flow ------------------
__global__ void warp_k(const float* __restrict__ feat2, const float* __restrict__ pred,
                       float* __restrict__ out)
{
    int idx = blockIdx.x*256 + threadIdx.x;
    int b = idx / HWP, p = idx % HWP;
    int yi = p / WW, xi = p % WW;
    float fx = pred[(size_t)(b*3 + 0)*HWP + p];
    float fy = pred[(size_t)(b*3 + 1)*HWP + p];
    float vl = pred[(size_t)(b*3 + 2)*HWP + p];
    float vald = 1.f / (1.f + expf(-vl));
    float px = xi + fx, py = yi + fy;
    float x0 = floorf(px), y0 = floorf(py);
    float wx = px - x0, wy = py - y0;

    float cx[2] = {x0, x0 + 1.f};
    float cy[2] = {y0, y0 + 1.f};
    float vxf[2], vyf[2];
    int xcl[2], ycl[2];
    #pragma unroll
    for (int k = 0; k < 2; k++) {
        vxf[k] = (cx[k] >= 0.f && cx[k] <= (float)(WW - 1)) ? 1.f : 0.f;
        vyf[k] = (cy[k] >= 0.f && cy[k] <= (float)(HH - 1)) ? 1.f : 0.f;
        int xv = (int)cx[k]; xv = xv < 0 ? 0 : (xv > WW-1 ? WW-1 : xv); xcl[k] = xv;
        int yv = (int)cy[k]; yv = yv < 0 ? 0 : (yv > HH-1 ? HH-1 : yv); ycl[k] = yv;
    }
    float wv[4];
    wv[0] = (1.f - wx)*(1.f - wy) * vxf[0]*vyf[0];
    wv[1] = wx*(1.f - wy)         * vxf[1]*vyf[0];
    wv[2] = (1.f - wx)*wy         * vxf[0]*vyf[1];
    wv[3] = wx*wy                 * vxf[1]*vyf[1];
    int off[4];
    off[0] = ycl[0]*WW + xcl[0];
    off[1] = ycl[0]*WW + xcl[1];
    off[2] = ycl[1]*WW + xcl[0];
    off[3] = ycl[1]*WW + xcl[1];

    const float* f2b = feat2 + (size_t)b*CCH*HWP;
    #pragma unroll 4
    for (int c = 0; c < CCH; c++) {
        const float* fc = f2b + (size_t)c*HWP;
        float v = wv[0]*fc[off[0]] + wv[1]*fc[off[1]] + wv[2]*fc[off[2]] + wv[3]*fc[off[3]];
        out[ALIGNED_OFF + ((size_t)(b*CCH + c))*HWP + p] = v * vald;
    }
    out[FLOW_OFF + (size_t)(b*2 + 0)*HWP + p] = fx;
    out[FLOW_OFF + (size_t)(b*2 + 1)*HWP + p] = fy;
}

// ---------------- cost volume: 3 dy-groups of 3, acc[27] ----------------------
__global__ void __launch_bounds__(256) costvol_k(const float* __restrict__ f1,
                                                 const float* __restrict__ al,
                                                 float* __restrict__ cv)
{
    const int CK = 4;
    __shared__ float s_f1[CK][16][16];
    __shared__ float s_al[CK][18][24];
    int b = blockIdx.z;
    int dyg = blockIdx.y;                  // 0..2 -> dy in {3*dyg, 3*dyg+1, 3*dyg+2}
    int tile = blockIdx.x;
    int X0 = (tile & 7) * 16;
    int Y0 = (tile >> 3) * 16;
    int tid = threadIdx.x;
    int ty = tid >> 4, tx = tid & 15;
    float acc[27];
    #pragma unroll
    for (int d = 0; d < 27; d++) acc[d] = 0.f;

    int dy0 = dyg*3;
    for (int c0 = 0; c0 < CCH; c0 += CK) {
        for (int i = tid; i < CK*256; i += 256) {
            int c = i >> 8, r = (i >> 4) & 15, col = i & 15;
            s_f1[c][r][col] = f1[((size_t)(b*CCH + c0 + c))*HWP + (Y0 + r)*WW + X0 + col];
        }
        for (int i = tid; i < CK*432; i += 256) {
            int c = i / 432, rem = i % 432, r = rem / 24, col = rem % 24;
            int gy = Y0 + r + dy0 - RRAD;
            int gx = X0 + col - RRAD;
            float v = 0.f;
            if (gy >= 0 && gy < HH && gx >= 0 && gx < WW)
                v = al[((size_t)(b*CCH + c0 + c))*HWP + gy*WW + gx];
            s_al[c][r][col] = v;
        }
        __syncthreads();
        #pragma unroll
        for (int c = 0; c < CK; c++) {
            float f = s_f1[c][ty][tx];
            #pragma unroll
            for (int dyi = 0; dyi < 3; dyi++)
                #pragma unroll
                for (int dx = 0; dx < 9; dx++)
                    acc[dyi*9 + dx] += f * s_al[c][ty + dyi][tx + dx];
        }
        __syncthreads();
    }
    int p = (Y0 + ty)*WW + X0 + tx;
    #pragma unroll
    for (int dyi = 0; dyi < 3; dyi++)
        #pragma unroll
        for (int dx = 0; dx < 9; dx++)
            cv[((size_t)(b*81 + (dy0 + dyi)*9 + dx))*HWP + p] = acc[dyi*9 + dx] * (1.0f/CCH);
}

// ---------------- 1x1 conv (MODE 0: plain in, MODE 1: |inA - inB|) ------------
template<int CIN, int MODE>
__global__ void conv1x1_k(const float* __restrict__ inA, const float* __restrict__ inB,
                          const float* __restrict__ wgt, float* __restrict__ out, int c_off)
{
    const int CK = 8;
    __shared__ float s_w[CK][64];
    __shared__ float s_x[CK][128];
    int tid = threadIdx.x;
    int P0 = blockIdx.x * 128;
    int b = P0 / HWP;
    int p0 = P0 % HWP;
    int co_g = tid >> 5;
    int pg = tid & 31;
    float acc[8][4];
    #pragma unroll
    for (int k = 0; k < 8; k++)
        #pragma unroll
        for (int j = 0; j < 4; j++) acc[k][j] = 0.f;

    for (int c0 = 0; c0 < CIN; c0 += CK) {
        for (int i = tid; i < CK*64; i += 256) {
            int c = i >> 6, o = i & 63;
            int ci = c0 + c;
            s_w[c][o] = (ci < CIN) ? wgt[(size_t)o*CIN + ci] : 0.f;
        }
        for (int i = tid; i < CK*128; i += 256) {
            int c = i >> 7, px = i & 127;
            int ci = c0 + c;
            float v = 0.f;
            if (ci < CIN) {
                if (MODE == 0) {
                    v = inA[((size_t)(b*CIN + ci))*HWP + p0 + px];
                } else {
                    size_t gi = ((size_t)(b*CCH + ci))*HWP + p0 + px;
                    v = fabsf(inA[gi] - inB[gi]);
                }
            }
            s_x[c][px] = v;
        }
        __syncthreads();
        #pragma unroll
        for (int c = 0; c < CK; c++) {
            float4 wa = *(const float4*)&s_w[c][co_g*8];
            float4 wb = *(const float4*)&s_w[c][co_g*8 + 4];
            float4 x4 = *(const float4*)&s_x[c][pg*4];
            float w8[8] = {wa.x, wa.y, wa.z, wa.w, wb.x, wb.y, wb.z, wb.w};
            float xv[4] = {x4.x, x4.y, x4.z, x4.w};
            #pragma unroll
            for (int k = 0; k < 8; k++)
                #pragma unroll
                for (int j = 0; j < 4; j++) acc[k][j] += w8[k]*xv[j];
        }
        __syncthreads();
    }
    #pragma unroll
    for (int k = 0; k < 8; k++) {
        int oc = c_off + co_g*8 + k;
        float4 r4 = make_float4(acc[k][0], acc[k][1], acc[k][2], acc[k][3]);
        *(float4*)&out[((size_t)(b*CCH + oc))*HWP + p0 + pg*4] = r4;
    }
}

// ---------------- fused fus_w2 -> lam weight ----------------------------------
__global__ void weff_k(const float* __restrict__ fus_w2, const float* __restrict__ lam_w,
                       float* __restrict__ weff)
{
    int c = threadIdx.x;
    float s = 0.f;
    for (int o = 0; o < 128; o++) s += lam_w[o] * fus_w2[(size_t)o*128 + c];
    weff[c] = s;
}

// ---------------- lam = sigmoid(dot(weff, relu(GN(f))) + lam_b) ---------------
__global__ void lam_gn_k(const float* __restrict__ f, const float* __restrict__ weff,
                         const float* __restrict__ gamma, const float* __restrict__ beta,
                         const float* __restrict__ stats, const float* __restrict__ lam_b,
                         float* __restrict__ out)
{
    __shared__ float sw[128], sa[128], sb[128];
    int tid = threadIdx.x;
    int idx = blockIdx.x*256 + tid;
    int b = idx / HWP, p = idx % HWP;
    if (tid < 128) {
        int c = tid;
        float mm = stats[(b*32 + c/4)*2];
        float rr = stats[(b*32 + c/4)*2 + 1];
        float ga = gamma[c]*rr;
        sw[c] = weff[c];
        sa[c] = ga;
        sb[c] = beta[c] - mm*ga;
    }
    __syncthreads();
    float s = lam_b[0];
    const float* fb = f + (size_t)b*CCH*HWP + p;
    #pragma unroll 4
    for (int c = 0; c < CCH; c++) {
        float v = fmaxf(fmaf(fb[(size_t)c*HWP], sa[c], sb[c]), 0.f);
        s = fmaf(sw[c], v, s);
    }
    out[LAM_OFF + idx] = 1.f / (1.f + expf(-s));
}

// ---------------- launch ------------------------------------------------------
extern "C" void kernel_launch(void* const* d_in, const int* in_sizes, int n_in,
                              void* d_out, int out_size)
{
    const float* feat1    = (const float*)d_in[0];
    const float* feat2    = (const float*)d_in[1];
    const float* off_w1   = (const float*)d_in[2];
    const float* off_g1   = (const float*)d_in[3];
    const float* off_b1   = (const float*)d_in[4];
    const float* off_w2   = (const float*)d_in[5];
    const float* off_g2   = (const float*)d_in[6];
    const float* off_b2   = (const float*)d_in[7];
    const float* off_w3   = (const float*)d_in[8];
    const float* off_bias3= (const float*)d_in[9];
    const float* corr_w   = (const float*)d_in[10];
    const float* corr_g   = (const float*)d_in[11];
    const float* corr_b   = (const float*)d_in[12];
    const float* diff_w   = (const float*)d_in[13];
    const float* diff_g   = (const float*)d_in[14];
    const float* diff_b   = (const float*)d_in[15];
    const float* fus_w1   = (const float*)d_in[16];
    const float* fus_g1   = (const float*)d_in[17];
    const float* fus_b1   = (const float*)d_in[18];
    const float* fus_w2   = (const float*)d_in[19];
    const float* lam_w    = (const float*)d_in[20];
    const float* lam_b    = (const float*)d_in[21];
    float* out = (float*)d_out;

    float *x1, *x2, *pred, *cv, *cd, *f, *weff, *stats;
    __nv_bfloat16 *wh, *wl, *a1h, *a1l, *a2h, *a2l, *a3h, *a3l;
    cudaGetSymbolAddress((void**)&x1,   g_x1);
    cudaGetSymbolAddress((void**)&x2,   g_x2);
    cudaGetSymbolAddress((void**)&pred, g_pred);
    cudaGetSymbolAddress((void**)&cv,   g_cv);
    cudaGetSymbolAddress((void**)&cd,   g_cd);
    cudaGetSymbolAddress((void**)&f,    g_f);
    cudaGetSymbolAddress((void**)&weff, g_weff);
    cudaGetSymbolAddress((void**)&stats,g_stats);
    cudaGetSymbolAddress((void**)&wh,   g_wh);
    cudaGetSymbolAddress((void**)&wl,   g_wl);
    cudaGetSymbolAddress((void**)&a1h,  g_a1h);
    cudaGetSymbolAddress((void**)&a1l,  g_a1l);
    cudaGetSymbolAddress((void**)&a2h,  g_a2h);
    cudaGetSymbolAddress((void**)&a2l,  g_a2l);
    cudaGetSymbolAddress((void**)&a3h,  g_a3h);
    cudaGetSymbolAddress((void**)&a3l,  g_a3l);

    const int SMEM_128 = 2*(2*9*128*16*2) + 2*(2*5440*2);   // 190976
    const int SMEM_64  = 2*(2*9*64*16*2)  + 2*(2*5440*2);   // 117248
    cudaFuncSetAttribute(conv3x3_mma_k<16,128>, cudaFuncAttributeMaxDynamicSharedMemorySize, SMEM_128);
    cudaFuncSetAttribute(conv3x3_mma_k<8,128>,  cudaFuncAttributeMaxDynamicSharedMemorySize, SMEM_128);
    cudaFuncSetAttribute(conv3x3_mma_k<8,64>,   cudaFuncAttributeMaxDynamicSharedMemorySize, SMEM_64);

    // weight prep
    wprep_k<<<(128*256*9 + 255)/256, 256>>>(off_w1, wh + WOFF1, wl + WOFF1, 128, 256);
    wprep_k<<<( 64*128*9 + 255)/256, 256>>>(off_w2, wh + WOFF2, wl + WOFF2,  64, 128);
    wprep_k<<<(128*128*9 + 255)/256, 256>>>(fus_w1, wh + WOFFF, wl + WOFFF, 128, 128);

    // pack conv1 inputs (feat1 -> groups 0..7, feat2 -> 8..15), one launch
    pack2_k<<<dim3(HWP/256, 16, BB), 256>>>(feat1, feat2, a1h, a1l);

    // conv1 (256 -> 128) + GN + SiLU -> packed A2
    conv3x3_mma_k<16,128><<<dim3(64, 1, BB), 256, SMEM_128>>>(a1h, a1l, wh + WOFF1, wl + WOFF1, x1, 128);
    gn_stats_k<<<256, 256>>>(x1, 128, 0, 4, stats + 0*512);
    gn_apply_pack_k<<<dim3(HWP/256, 8, BB), 256>>>(x1, off_g1, off_b1, stats + 0*512,
                                                   128, 0, 4, 0, a2h, a2l, 0, 8);

    // conv2 (128 -> 64) + GN + SiLU (fp32, for scalar conv3)
    conv3x3_mma_k<8,64><<<dim3(64, 1, BB), 256, SMEM_64>>>(a2h, a2l, wh + WOFF2, wl + WOFF2, x2, 64);
    gn_stats_k<<<256, 256>>>(x2, 64, 0, 2, stats + 1*512);
    gn_apply_k<<<BB*64*HWP/256, 256>>>(x2, off_g2, off_b2, stats + 1*512, 64, 0, 64, 2, 0);

    // conv3 (64 -> 3) + bias
    conv3_k<<<dim3(64, 1, BB), 256>>>(x2, off_w3, off_bias3, pred);

    // warp -> aligned + flow (into d_out)
    warp_k<<<BB*HWP/256, 256>>>(feat2, pred, out);

    // cost volume (3 dy-groups)
    costvol_k<<<dim3(64, 3, BB), 256>>>(feat1, out + ALIGNED_OFF, cv);

    // corr 1x1 (81 -> 64) into cd[0:64], diff 1x1 (128 -> 64) into cd[64:128]
    conv1x1_k<81, 0><<<BB*HWP/128, 256>>>(cv, nullptr, corr_w, cd, 0);
    conv1x1_k<128, 1><<<BB*HWP/128, 256>>>(feat1, out + ALIGNED_OFF, diff_w, cd, 64);

    // GN + relu on each half -> packed A3
    gn_stats_k<<<256, 256>>>(cd, 128, 0, 2, stats + 2*512);
    gn_stats_k<<<256, 256>>>(cd, 128, 64, 2, stats + 3*512);
    gn_apply_pack_k<<<dim3(HWP/256, 4, BB), 256>>>(cd, corr_g, corr_b, stats + 2*512,
                                                   128, 0, 2, 1, a3h, a3l, 0, 8);
    gn_apply_pack_k<<<dim3(HWP/256, 4, BB), 256>>>(cd, diff_g, diff_b, stats + 3*512,
                                                   128, 64, 2, 1, a3h, a3l, 4, 8);

    // fus1 (128 -> 128), raw f; GN fused into lam
    conv3x3_mma_k<8,128><<<dim3(64, 1, BB), 256, SMEM_128>>>(a3h, a3l, wh + WOFFF, wl + WOFFF, f, 128);
    gn_stats_k<<<256, 256>>>(f, 128, 0, 4, stats + 4*512);

    // fused fus2 + GN + relu + lam
    weff_k<<<1, 128>>>(fus_w2, lam_w, weff);
    lam_gn_k<<<BB*HWP/256, 256>>>(f, weff, fus_g1, fus_b1, stats + 4*512, lam_b, out);
}

// round 11
// speedup vs baseline: 1.2827x; 1.0272x over previous
#include <cuda_runtime.h>
#include <cuda_bf16.h>
#include <math.h>
#include <stdint.h>

#define BB 8
#define CCH 128
#define HH 128
#define WW 128
#define HWP (HH*WW)
#define RRAD 4

// ---------------- scratch (device globals; no allocation allowed) -------------
__device__ float g_x1[BB*CCH*HWP];     // conv1 out (fp32, pre-GN)
__device__ float g_x2[BB*64*HWP];      // conv2 out (raw; GN fused into conv3)
__device__ float g_pred[BB*3*HWP];     // conv3 out (flow + validity logit)
__device__ float g_cv[BB*81*HWP];      // cost volume
__device__ float g_cd[BB*CCH*HWP];     // ce (ch 0-63) + de (ch 64-127), pre-GN
__device__ float g_f[BB*CCH*HWP];      // fus1 out (raw, pre-GN)
__device__ float g_weff[CCH];          // fused fus_w2 -> lam weight
__device__ float g_red[5*256*2];       // 5 GN sites x (B*32 groups) x (sum, sumsq)
__device__ float g_stats[5*256*2];     // 5 GN sites x (B*32 groups) x (mean, rstd)

// packed bf16 hi/lo activations: [b][ch16][y][x][c16]
__device__ __nv_bfloat16 g_a1h[(size_t)BB*16*HWP*16], g_a1l[(size_t)BB*16*HWP*16]; // conv1 in (256ch)
__device__ __nv_bfloat16 g_a2h[(size_t)BB*8*HWP*16],  g_a2l[(size_t)BB*8*HWP*16];  // conv2 in (128ch)
__device__ __nv_bfloat16 g_a3h[(size_t)BB*8*HWP*16],  g_a3l[(size_t)BB*8*HWP*16];  // fus1 in (128ch)

// bf16-split weights, pre-permuted: [cin_chunk][tap(9)][cout_all][cin16]
#define WOFF1 0
#define WOFF2 294912            // conv1: 128*256*9
#define WOFFF (294912 + 73728)  // conv2: 64*128*9
#define WTOT  (294912 + 73728 + 147456)
__device__ __nv_bfloat16 g_wh[WTOT];
__device__ __nv_bfloat16 g_wl[WTOT];

#define ALIGNED_OFF 0
#define FLOW_OFF (BB*CCH*HWP)
#define LAM_OFF  (FLOW_OFF + BB*2*HWP)

// ---------------- mma / cp.async helpers --------------------------------------
__device__ __forceinline__ void ldsm4(uint32_t& r0, uint32_t& r1, uint32_t& r2, uint32_t& r3,
                                      uint32_t addr) {
    asm volatile("ldmatrix.sync.aligned.m8n8.x4.shared.b16 {%0,%1,%2,%3},[%4];"
        : "=r"(r0), "=r"(r1), "=r"(r2), "=r"(r3) : "r"(addr));
}
__device__ __forceinline__ void mma16816(float* c, const uint32_t* a, const uint32_t* b) {
    asm volatile("mma.sync.aligned.m16n8k16.row.col.f32.bf16.bf16.f32 "
        "{%0,%1,%2,%3},{%4,%5,%6,%7},{%8,%9},{%0,%1,%2,%3};"
        : "+f"(c[0]), "+f"(c[1]), "+f"(c[2]), "+f"(c[3])
        : "r"(a[0]), "r"(a[1]), "r"(a[2]), "r"(a[3]), "r"(b[0]), "r"(b[1]));
}
__device__ __forceinline__ void cpasync16(uint32_t dst, const void* src) {
    asm volatile("cp.async.cg.shared.global [%0],[%1],16;" :: "r"(dst), "l"(src));
}
__device__ __forceinline__ void cpcommit() { asm volatile("cp.async.commit_group;"); }
template<int N> __device__ __forceinline__ void cpwait() {
    asm volatile("cp.async.wait_group %0;" :: "n"(N));
}

// ---------------- zero the reduction buffer -----------------------------------
__global__ void zero_red_k(float* __restrict__ red)
{
    int i = blockIdx.x*512 + threadIdx.x*2;
    red[i] = 0.f;
    red[i+1] = 0.f;
}

// ---------------- two-stage GN stats: float4 partial sums ---------------------
// grid: (8 slices, 256 groups). group = b*32+g, each group covers cpg*HWP floats.
__global__ void gn_stats2_k(const float* __restrict__ x, int Ctot, int c_off, int cpg,
                            float* __restrict__ red)
{
    int bg = blockIdx.y;
    int b = bg >> 5, g = bg & 31;
    int slice = blockIdx.x;
    int tid = threadIdx.x;
    int N = cpg * HWP;
    int NS = N / 8;                     // floats per slice (8192 or 4096)
    const float4* base = (const float4*)(x + ((size_t)(b*Ctot + c_off + g*cpg))*HWP
                                           + (size_t)slice*NS);
    float s = 0.f, s2 = 0.f;
    for (int i = tid; i < NS/4; i += 256) {
        float4 v = base[i];
        s  += v.x + v.y + v.z + v.w;
        s2 += v.x*v.x + v.y*v.y + v.z*v.z + v.w*v.w;
    }
    __shared__ float rs[256], rs2[256];
    rs[tid] = s; rs2[tid] = s2;
    __syncthreads();
    for (int st = 128; st > 0; st >>= 1) {
        if (tid < st) { rs[tid] += rs[tid + st]; rs2[tid] += rs2[tid + st]; }
        __syncthreads();
    }
    if (tid == 0) {
        atomicAdd(&red[bg*2],     rs[0]);
        atomicAdd(&red[bg*2 + 1], rs2[0]);
    }
}

// ---------------- finalize: (sum, sumsq) -> (mean, rstd) ----------------------
__global__ void finalize_k(const float* __restrict__ red, float* __restrict__ stats, int N)
{
    int i = threadIdx.x;   // 256 = b*32+g
    float invN = 1.f / (float)N;
    float m = red[i*2] * invN;
    float var = red[i*2+1]*invN - m*m;
    stats[i*2]   = m;
    stats[i*2+1] = rsqrtf(fmaxf(var, 0.f) + 1e-5f);
}

// ---------------- weight prep: fp32 [COUT][CIN][9] -> split bf16 permuted -----
__global__ void wprep_k(const float* __restrict__ w, __nv_bfloat16* __restrict__ wh,
                        __nv_bfloat16* __restrict__ wl, int COUT, int CIN)
{
    int idx = blockIdx.x*256 + threadIdx.x;
    int total = COUT*CIN*9;
    if (idx >= total) return;
    int c16 = idx & 15;
    int co  = (idx >> 4) % COUT;
    int rest = (idx >> 4) / COUT;    // ch*9 + tap
    int tap = rest % 9;
    int ch = rest / 9;
    int cin = ch*16 + c16;
    float v = w[((size_t)co*CIN + cin)*9 + tap];
    __nv_bfloat16 h = __float2bfloat16(v);
    wh[idx] = h;
    wl[idx] = __float2bfloat16(v - __bfloat162float(h));
}

// ---------------- pack feat1+feat2 -> bf16 hi/lo packed (one launch) ----------
__global__ void pack2_k(const float* __restrict__ src1, const float* __restrict__ src2,
                        __nv_bfloat16* __restrict__ dh, __nv_bfloat16* __restrict__ dl)
{
    int p = blockIdx.x*256 + threadIdx.x;
    int by = blockIdx.y, b = blockIdx.z;          // by 0..15
    const float* src = (by < 8) ? src1 : src2;
    int cb = (by & 7)*16;
    union { uint4 u[2]; __nv_bfloat16 h[16]; } ph, pl;
    #pragma unroll
    for (int c = 0; c < 16; c++) {
        float v = src[((size_t)(b*128 + cb + c))*HWP + p];
        __nv_bfloat16 hh = __float2bfloat16(v);
        ph.h[c] = hh;
        pl.h[c] = __float2bfloat16(v - __bfloat162float(hh));
    }
    size_t e = (((size_t)(b*16 + by))*HWP + p)*16;
    ((uint4*)(dh + e))[0] = ph.u[0]; ((uint4*)(dh + e))[1] = ph.u[1];
    ((uint4*)(dl + e))[0] = pl.u[0]; ((uint4*)(dl + e))[1] = pl.u[1];
}

// ---------------- GN apply + act -> bf16 hi/lo packed -------------------------
__global__ void gn_apply_pack_k(const float* __restrict__ x, const float* __restrict__ gamma,
                                const float* __restrict__ beta, const float* __restrict__ stats,
                                int Ctot, int c_off_src, int cpg, int act,
                                __nv_bfloat16* __restrict__ dh, __nv_bfloat16* __restrict__ dl,
                                int ch_off, int NCHT)
{
    int p = blockIdx.x*256 + threadIdx.x;
    int by = blockIdx.y, b = blockIdx.z;
    union { uint4 u[2]; __nv_bfloat16 h[16]; } ph, pl;
    #pragma unroll
    for (int c = 0; c < 16; c++) {
        int cl = by*16 + c;
        int g = cl / cpg;
        float m = stats[(b*32 + g)*2];
        float r = stats[(b*32 + g)*2 + 1];
        float v = x[((size_t)(b*Ctot + c_off_src + cl))*HWP + p];
        v = (v - m) * r * gamma[cl] + beta[cl];
        if (act == 0) v = v / (1.f + expf(-v));
        else          v = fmaxf(v, 0.f);
        __nv_bfloat16 hh = __float2bfloat16(v);
        ph.h[c] = hh;
        pl.h[c] = __float2bfloat16(v - __bfloat162float(hh));
    }
    size_t e = (((size_t)(b*NCHT + ch_off + by))*HWP + p)*16;
    ((uint4*)(dh + e))[0] = ph.u[0]; ((uint4*)(dh + e))[1] = ph.u[1];
    ((uint4*)(dl + e))[0] = pl.u[0]; ((uint4*)(dl + e))[1] = pl.u[1];
}

// ---------------- tensor-core 3x3 conv, pad=1, cp.async double-buffered -------
template<int NCH, int COUTB>
__global__ void __launch_bounds__(256)
conv3x3_mma_k(const __nv_bfloat16* __restrict__ aph, const __nv_bfloat16* __restrict__ apl,
              const __nv_bfloat16* __restrict__ gwh, const __nv_bfloat16* __restrict__ gwl,
              float* __restrict__ out, int COUT)
{
    const int MF = COUTB/32;
    const int WPL = 9*COUTB*16;               // weight plane, elements
    const int WPLB = WPL*2;                   // weight plane, bytes
    const int WBUF = 2*WPLB;                  // one weight buffer (hi+lo), bytes
    const int APLB = 5440*2;                  // act plane bytes
    const int ABUF = 2*APLB;                  // one act buffer (hi+lo), bytes
    const int ABASE = 2*WBUF;
    extern __shared__ char dsm[];

    int b = blockIdx.z, tile = blockIdx.x;
    int X0 = (tile & 3) * 32;
    int Y0 = (tile >> 2) * 8;
    int tid = threadIdx.x;
    int wid = tid >> 5, lane = tid & 31;
    int cw = wid & 1, pw = wid >> 1;
    int g = lane >> 2, t = lane & 3;

    uint32_t sm_base = (uint32_t)__cvta_generic_to_shared(dsm);

    float acc[MF][8][4];
    #pragma unroll
    for (int mf = 0; mf < MF; mf++)
        #pragma unroll
        for (int j = 0; j < 8; j++)
            #pragma unroll
            for (int k = 0; k < 4; k++) acc[mf][j][k] = 0.f;

    int m = lane >> 3, ri = lane & 7;
    int a_kb = (m >> 1) * 8;
    int a_corow = (m & 1) * 8 + ri;
    uint32_t b_off[4];
    {
        int mm = lane >> 3;
        int rb = lane & 7;
        #pragma unroll
        for (int jp = 0; jp < 4; jp++) {
            int j = jp*2 + (mm >> 1);
            int kb = (mm & 1) * 8;
            int n = j*8 + rb;
            int rloc = n >> 5, xb = n & 31;
            b_off[jp] = (uint32_t)((((pw*2 + rloc)*34 + xb)*16 + kb) * 2);
        }
    }

    auto stage = [&](int ch, int bf) {
        const char* sh = (const char*)(gwh + (size_t)ch*WPL);
        const char* sl = (const char*)(gwl + (size_t)ch*WPL);
        uint32_t wd = sm_base + bf*WBUF;
        const int NV = WPLB/16;
        for (int i = tid; i < NV; i += 256) {
            cpasync16(wd + i*16, sh + i*16);
            cpasync16(wd + WPLB + i*16, sl + i*16);
        }
        uint32_t ad = sm_base + ABASE + bf*ABUF;
        uint4* dah = (uint4*)(dsm + ABASE + bf*ABUF);
        uint4* dal = (uint4*)(dsm + ABASE + bf*ABUF + APLB);
        const uint4 z = make_uint4(0,0,0,0);
        size_t basee = ((size_t)(b*NCH + ch))*HWP;
        for (int i = tid; i < 680; i += 256) {
            int pos = i >> 1, half = i & 1;
            int r = pos / 34, col = pos % 34;
            int gy = Y0 + r - 1, gx = X0 + col - 1;
            if (gy >= 0 && gy < HH && gx >= 0 && gx < WW) {
                size_t e = (basee + gy*WW + gx)*16 + half*8;
                cpasync16(ad + (pos*2 + half)*16, aph + e);
                cpasync16(ad + APLB + (pos*2 + half)*16, apl + e);
            } else {
                dah[pos*2 + half] = z;
                dal[pos*2 + half] = z;
            }
        }
    };

    stage(0, 0);
    cpcommit();

    for (int ch = 0; ch < NCH; ch++) {
        if (ch + 1 < NCH) { stage(ch + 1, (ch + 1) & 1); cpcommit(); cpwait<1>(); }
        else              { cpwait<0>(); }
        __syncthreads();

        int bf = ch & 1;
        uint32_t swb = sm_base + bf*WBUF;
        uint32_t sab = sm_base + ABASE + bf*ABUF;

        #pragma unroll
        for (int tap = 0; tap < 9; tap++) {
            int ky = tap / 3, kx = tap - ky*3;
            uint32_t ah[MF][4], al[MF][4];
            #pragma unroll
            for (int mf = 0; mf < MF; mf++) {
                uint32_t off = (uint32_t)(((tap*COUTB + cw*(COUTB/2) + mf*16 + a_corow)*16 + a_kb) * 2);
                ldsm4(ah[mf][0], ah[mf][1], ah[mf][2], ah[mf][3], swb + off);
                ldsm4(al[mf][0], al[mf][1], al[mf][2], al[mf][3], swb + (uint32_t)WPLB + off);
            }
            uint32_t tshift = (uint32_t)(((ky*34 + kx)*16) * 2);
            #pragma unroll
            for (int jp = 0; jp < 4; jp++) {
                uint32_t ba = sab + b_off[jp] + tshift;
                uint32_t bh[4], bl[4];
                ldsm4(bh[0], bh[1], bh[2], bh[3], ba);
                ldsm4(bl[0], bl[1], bl[2], bl[3], ba + (uint32_t)APLB);
                #pragma unroll
                for (int jj = 0; jj < 2; jj++) {
                    int j = jp*2 + jj;
                    #pragma unroll
                    for (int mf = 0; mf < MF; mf++) {
                        mma16816(acc[mf][j], ah[mf], &bh[jj*2]);
                        mma16816(acc[mf][j], ah[mf], &bl[jj*2]);
                        mma16816(acc[mf][j], al[mf], &bh[jj*2]);
                    }
                }
            }
        }
        __syncthreads();
    }

    // ---- writeback ----
    #pragma unroll
    for (int mf = 0; mf < MF; mf++)
        #pragma unroll
        for (int j = 0; j < 8; j++) {
            int n0 = j*8 + 2*t;
            int rloc = n0 >> 5, x = n0 & 31;
            int py = Y0 + pw*2 + rloc, px = X0 + x;
            int cout0 = cw*(COUTB/2) + mf*16 + g;
            float2 v01 = make_float2(acc[mf][j][0], acc[mf][j][1]);
            float2 v23 = make_float2(acc[mf][j][2], acc[mf][j][3]);
            *(float2*)&out[((size_t)(b*COUT + cout0))*HWP + py*WW + px] = v01;
            *(float2*)&out[((size_t)(b*COUT + cout0 + 8))*HWP + py*WW + px] = v23;
        }
}

// ---------------- conv3: 64 -> 3, 3x3 pad=1, + bias; GN+SiLU on x2 inline -----
__global__ void conv3_k(const float* __restrict__ x, const float* __restrict__ w,
                        const float* __restrict__ bias, float* __restrict__ pred,
                        const float* __restrict__ gamma, const float* __restrict__ beta,
                        const float* __restrict__ stats)
{
    const int CK = 8;
    __shared__ float s_in[CK][18][20];
    __shared__ float s_w[CK][9][4];
    int b = blockIdx.z;
    int X0 = (blockIdx.x & 7) * 16;
    int Y0 = (blockIdx.x >> 3) * 16;
    int tid = threadIdx.x;
    int ty = tid >> 4, tx = tid & 15;
    float acc[3] = {0.f, 0.f, 0.f};

    for (int c0 = 0; c0 < 64; c0 += CK) {
        for (int i = tid; i < CK*18*18; i += 256) {
            int c = i / 324, rem = i % 324, r = rem / 18, col = rem % 18;
            int gy = Y0 + r - 1, gx = X0 + col - 1;
            float v = 0.f;
            if (gy >= 0 && gy < HH && gx >= 0 && gx < WW) {
                int cc = c0 + c;
                float m  = stats[(b*32 + (cc >> 1))*2];
                float rr = stats[(b*32 + (cc >> 1))*2 + 1];
                v = x[((size_t)(b*64 + cc))*HWP + gy*WW + gx];
                v = (v - m) * rr * gamma[cc] + beta[cc];
                v = v / (1.f + expf(-v));      // SiLU
            }
            s_in[c][r][col] = v;
        }
        for (int i = tid; i < CK*9*3; i += 256) {
            int c = i / 27, rem = i % 27, tap = rem / 3, o = rem % 3;
            s_w[c][tap][o] = w[(size_t)o*64*9 + (c0 + c)*9 + tap];
        }
        __syncthreads();
        #pragma unroll
        for (int c = 0; c < CK; c++)
            #pragma unroll
            for (int ky = 0; ky < 3; ky++)
                #pragma unroll
                for (int kx = 0; kx < 3; kx++) {
                    float v = s_in[c][ty + ky][tx + kx];
                    acc[0] += v * s_w[c][ky*3 + kx][0];
                    acc[1] += v * s_w[c][ky*3 + kx][1];
                    acc[2] += v * s_w[c][ky*3 + kx][2];
                }
        __syncthreads();
    }
    int p = (Y0 + ty)*WW + X0 + tx;
    pred[(size_t)(b*3 + 0)*HWP + p] = acc[0] + bias[0];
    pred[(size_t)(b*3 + 1)*HWP + p] = acc[1] + bias[1];
    pred[(size_t)(b*3 + 2)*HWP + p] = acc[2] + bias[2];
}

// ---------------- bilinear warp * validity; also writes flow ------------------
__global__ void warp_k(const float* __restrict__ feat2, const float* __restrict__ pred,
                       float* __restrict__ out)
{
    int idx = blockIdx.x*256 + threadIdx.x;
    int b = idx / HWP, p = idx % HWP;
    int yi = p / WW, xi = p % WW;
    float fx = pred[(size_t)(b*3 + 0)*HWP + p];
    float fy = pred[(size_t)(b*3 + 1)*HWP + p];
    float vl = pred[(size_t)(b*3 + 2)*HWP + p];
    float vald = 1.f / (1.f + expf(-vl));
    float px = xi + fx, py = yi + fy;
    float x0 = floorf(px), y0 = floorf(py);
    float wx = px - x0, wy = py - y0;

    float cx[2] = {x0, x0 + 1.f};
    float cy[2] = {y0, y0 + 1.f};
    float vxf[2], vyf[2];
    int xcl[2], ycl[2];
    #pragma unroll
    for (int k = 0; k < 2; k++) {
        vxf[k] = (cx[k] >= 0.f && cx[k] <= (float)(WW - 1)) ? 1.f : 0.f;
        vyf[k] = (cy[k] >= 0.f && cy[k] <= (float)(HH - 1)) ? 1.f : 0.f;
        int xv = (int)cx[k]; xv = xv < 0 ? 0 : (xv > WW-1 ? WW-1 : xv); xcl[k] = xv;
        int yv = (int)cy[k]; yv = yv < 0 ? 0 : (yv > HH-1 ? HH-1 : yv); ycl[k] = yv;
    }
    float wv[4];
    wv[0] = (1.f - wx)*(1.f - wy) * vxf[0]*vyf[0];
    wv[1] = wx*(1.f - wy)         * vxf[1]*vyf[0];
    wv[2] = (1.f - wx)*wy         * vxf[0]*vyf[1];
    wv[3] = wx*wy                 * vxf[1]*vyf[1];
    int off[4];
    off[0] = ycl[0]*WW + xcl[0];
    off[1] = ycl[0]*WW + xcl[1];
    off[2] = ycl[1]*WW + xcl[0];
    off[3] = ycl[1]*WW + xcl[1];

    const float* f2b = feat2 + (size_t)b*CCH*HWP;
    #pragma unroll 4
    for (int c = 0; c < CCH; c++) {
        const float* fc = f2b + (size_t)c*HWP;
        float v = wv[0]*fc[off[0]] + wv[1]*fc[off[1]] + wv[2]*fc[off[2]] + wv[3]*fc[off[3]];
        out[ALIGNED_OFF + ((size_t)(b*CCH + c))*HWP + p] = v * vald;
    }
    out[FLOW_OFF + (size_t)(b*2 + 0)*HWP + p] = fx;
    out[FLOW_OFF + (size_t)(b*2 + 1)*HWP + p] = fy;
}

// ---------------- cost volume: 3 dy-groups of 3, acc[27] ----------------------
__global__ void __launch_bounds__(256) costvol_k(const float* __restrict__ f1,
                                                 const float* __restrict__ al,
                                                 float* __restrict__ cv)
{
    const int CK = 4;
    __shared__ float s_f1[CK][16][16];
    __shared__ float s_al[CK][18][24];
    int b = blockIdx.z;
    int dyg = blockIdx.y;                  // 0..2 -> dy in {3*dyg, 3*dyg+1, 3*dyg+2}
    int tile = blockIdx.x;
    int X0 = (tile & 7) * 16;
    int Y0 = (tile >> 3) * 16;
    int tid = threadIdx.x;
    int ty = tid >> 4, tx = tid & 15;
    float acc[27];
    #pragma unroll
    for (int d = 0; d < 27; d++) acc[d] = 0.f;

    int dy0 = dyg*3;
    for (int c0 = 0; c0 < CCH; c0 += CK) {
        for (int i = tid; i < CK*256; i += 256) {
            int c = i >> 8, r = (i >> 4) & 15, col = i & 15;
            s_f1[c][r][col] = f1[((size_t)(b*CCH + c0 + c))*HWP + (Y0 + r)*WW + X0 + col];
        }
        for (int i = tid; i < CK*432; i += 256) {
            int c = i / 432, rem = i % 432, r = rem / 24, col = rem % 24;
            int gy = Y0 + r + dy0 - RRAD;
            int gx = X0 + col - RRAD;
            float v = 0.f;
            if (gy >= 0 && gy < HH && gx >= 0 && gx < WW)
                v = al[((size_t)(b*CCH + c0 + c))*HWP + gy*WW + gx];
            s_al[c][r][col] = v;
        }
        __syncthreads();
        #pragma unroll
        for (int c = 0; c < CK; c++) {
            float f = s_f1[c][ty][tx];
            #pragma unroll
            for (int dyi = 0; dyi < 3; dyi++)
                #pragma unroll
                for (int dx = 0; dx < 9; dx++)
                    acc[dyi*9 + dx] += f * s_al[c][ty + dyi][tx + dx];
        }
        __syncthreads();
    }
    int p = (Y0 + ty)*WW + X0 + tx;
    #pragma unroll
    for (int dyi = 0; dyi < 3; dyi++)
        #pragma unroll
        for (int dx = 0; dx < 9; dx++)
            cv[((size_t)(b*81 + (dy0 + dyi)*9 + dx))*HWP + p] = acc[dyi*9 + dx] * (1.0f/CCH);
}

// ---------------- 1x1 conv (MODE 0: plain in, MODE 1: |inA - inB|) ------------
template<int CIN, int MODE>
__global__ void conv1x1_k(const float* __restrict__ inA, const float* __restrict__ inB,
                          const float* __restrict__ wgt, float* __restrict__ out, int c_off)
{
    const int CK = 8;
    __shared__ float s_w[CK][64];
    __shared__ float s_x[CK][128];
    int tid = threadIdx.x;
    int P0 = blockIdx.x * 128;
    int b = P0 / HWP;
    int p0 = P0 % HWP;
    int co_g = tid >> 5;
    int pg = tid & 31;
    float acc[8][4];
    #pragma unroll
    for (int k = 0; k < 8; k++)
        #pragma unroll
        for (int j = 0; j < 4; j++) acc[k][j] = 0.f;

    for (int c0 = 0; c0 < CIN; c0 += CK) {
        for (int i = tid; i < CK*64; i += 256) {
            int c = i >> 6, o = i & 63;
            int ci = c0 + c;
            s_w[c][o] = (ci < CIN) ? wgt[(size_t)o*CIN + ci] : 0.f;
        }
        for (int i = tid; i < CK*128; i += 256) {
            int c = i >> 7, px = i & 127;
            int ci = c0 + c;
            float v = 0.f;
            if (ci < CIN) {
                if (MODE == 0) {
                    v = inA[((size_t)(b*CIN + ci))*HWP + p0 + px];
                } else {
                    size_t gi = ((size_t)(b*CCH + ci))*HWP + p0 + px;
                    v = fabsf(inA[gi] - inB[gi]);
                }
            }
            s_x[c][px] = v;
        }
        __syncthreads();
        #pragma unroll
        for (int c = 0; c < CK; c++) {
            float4 wa = *(const float4*)&s_w[c][co_g*8];
            float4 wb = *(const float4*)&s_w[c][co_g*8 + 4];
            float4 x4 = *(const float4*)&s_x[c][pg*4];
            float w8[8] = {wa.x, wa.y, wa.z, wa.w, wb.x, wb.y, wb.z, wb.w};
            float xv[4] = {x4.x, x4.y, x4.z, x4.w};
            #pragma unroll
            for (int k = 0; k < 8; k++)
                #pragma unroll
                for (int j = 0; j < 4; j++) acc[k][j] += w8[k]*xv[j];
        }
        __syncthreads();
    }
    #pragma unroll
    for (int k = 0; k < 8; k++) {
        int oc = c_off + co_g*8 + k;
        float4 r4 = make_float4(acc[k][0], acc[k][1], acc[k][2], acc[k][3]);
        *(float4*)&out[((size_t)(b*CCH + oc))*HWP + p0 + pg*4] = r4;
    }
}

// ---------------- fused fus_w2 -> lam weight ----------------------------------
__global__ void weff_k(const float* __restrict__ fus_w2, const float* __restrict__ lam_w,
                       float* __restrict__ weff)
{
    int c = threadIdx.x;
    float s = 0.f;
    for (int o = 0; o < 128; o++) s += lam_w[o] * fus_w2[(size_t)o*128 + c];
    weff[c] = s;
}

// ---------------- lam = sigmoid(dot(weff, relu(GN(f))) + lam_b) ---------------
__global__ void lam_gn_k(const float* __restrict__ f, const float* __restrict__ weff,
                         const float* __restrict__ gamma, const float* __restrict__ beta,
                         const float* __restrict__ stats, const float* __restrict__ lam_b,
                         float* __restrict__ out)
{
    __shared__ float sw[128], sa[128], sb[128];
    int tid = threadIdx.x;
    int idx = blockIdx.x*256 + tid;
    int b = idx / HWP, p = idx % HWP;
    if (tid < 128) {
        int c = tid;
        float mm = stats[(b*32 + c/4)*2];
        float rr = stats[(b*32 + c/4)*2 + 1];
        float ga = gamma[c]*rr;
        sw[c] = weff[c];
        sa[c] = ga;
        sb[c] = beta[c] - mm*ga;
    }
    __syncthreads();
    float s = lam_b[0];
    const float* fb = f + (size_t)b*CCH*HWP + p;
    #pragma unroll 4
    for (int c = 0; c < CCH; c++) {
        float v = fmaxf(fmaf(fb[(size_t)c*HWP], sa[c], sb[c]), 0.f);
        s = fmaf(sw[c], v, s);
    }
    out[LAM_OFF + idx] = 1.f / (1.f + expf(-s));
}

// ---------------- launch ------------------------------------------------------
extern "C" void kernel_launch(void* const* d_in, const int* in_sizes, int n_in,
                              void* d_out, int out_size)
{
    const float* feat1    = (const float*)d_in[0];
    const float* feat2    = (const float*)d_in[1];
    const float* off_w1   = (const float*)d_in[2];
    const float* off_g1   = (const float*)d_in[3];
    const float* off_b1   = (const float*)d_in[4];
    const float* off_w2   = (const float*)d_in[5];
    const float* off_g2   = (const float*)d_in[6];
    const float* off_b2   = (const float*)d_in[7];
    const float* off_w3   = (const float*)d_in[8];
    const float* off_bias3= (const float*)d_in[9];
    const float* corr_w   = (const float*)d_in[10];
    const float* corr_g   = (const float*)d_in[11];
    const float* corr_b   = (const float*)d_in[12];
    const float* diff_w   = (const float*)d_in[13];
    const float* diff_g   = (const float*)d_in[14];
    const float* diff_b   = (const float*)d_in[15];
    const float* fus_w1   = (const float*)d_in[16];
    const float* fus_g1   = (const float*)d_in[17];
    const float* fus_b1   = (const float*)d_in[18];
    const float* fus_w2   = (const float*)d_in[19];
    const float* lam_w    = (const float*)d_in[20];
    const float* lam_b    = (const float*)d_in[21];
    float* out = (float*)d_out;

    float *x1, *x2, *pred, *cv, *cd, *f, *weff, *red, *stats;
    __nv_bfloat16 *wh, *wl, *a1h, *a1l, *a2h, *a2l, *a3h, *a3l;
    cudaGetSymbolAddress((void**)&x1,   g_x1);
    cudaGetSymbolAddress((void**)&x2,   g_x2);
    cudaGetSymbolAddress((void**)&pred, g_pred);
    cudaGetSymbolAddress((void**)&cv,   g_cv);
    cudaGetSymbolAddress((void**)&cd,   g_cd);
    cudaGetSymbolAddress((void**)&f,    g_f);
    cudaGetSymbolAddress((void**)&weff, g_weff);
    cudaGetSymbolAddress((void**)&red,  g_red);
    cudaGetSymbolAddress((void**)&stats,g_stats);
    cudaGetSymbolAddress((void**)&wh,   g_wh);
    cudaGetSymbolAddress((void**)&wl,   g_wl);
    cudaGetSymbolAddress((void**)&a1h,  g_a1h);
    cudaGetSymbolAddress((void**)&a1l,  g_a1l);
    cudaGetSymbolAddress((void**)&a2h,  g_a2h);
    cudaGetSymbolAddress((void**)&a2l,  g_a2l);
    cudaGetSymbolAddress((void**)&a3h,  g_a3h);
    cudaGetSymbolAddress((void**)&a3l,  g_a3l);

    const int SMEM_128 = 2*(2*9*128*16*2) + 2*(2*5440*2);   // 190976
    const int SMEM_64  = 2*(2*9*64*16*2)  + 2*(2*5440*2);   // 117248
    cudaFuncSetAttribute(conv3x3_mma_k<16,128>, cudaFuncAttributeMaxDynamicSharedMemorySize, SMEM_128);
    cudaFuncSetAttribute(conv3x3_mma_k<8,128>,  cudaFuncAttributeMaxDynamicSharedMemorySize, SMEM_128);
    cudaFuncSetAttribute(conv3x3_mma_k<8,64>,   cudaFuncAttributeMaxDynamicSharedMemorySize, SMEM_64);

    // zero GN reduction buffer (5*512 floats, 5 blocks x 256 thr x 2)
    zero_red_k<<<5, 256>>>(red);

    // weight prep
    wprep_k<<<(128*256*9 + 255)/256, 256>>>(off_w1, wh + WOFF1, wl + WOFF1, 128, 256);
    wprep_k<<<( 64*128*9 + 255)/256, 256>>>(off_w2, wh + WOFF2, wl + WOFF2,  64, 128);
    wprep_k<<<(128*128*9 + 255)/256, 256>>>(fus_w1, wh + WOFFF, wl + WOFFF, 128, 128);

    // pack conv1 inputs (feat1 -> groups 0..7, feat2 -> 8..15), one launch
    pack2_k<<<dim3(HWP/256, 16, BB), 256>>>(feat1, feat2, a1h, a1l);

    // conv1 (256 -> 128) -> stats -> GN+SiLU pack -> A2
    conv3x3_mma_k<16,128><<<dim3(64, 1, BB), 256, SMEM_128>>>(a1h, a1l, wh + WOFF1, wl + WOFF1, x1, 128);
    gn_stats2_k<<<dim3(8, 256), 256>>>(x1, 128, 0, 4, red + 0*512);
    finalize_k<<<1, 256>>>(red + 0*512, stats + 0*512, 4*HWP);
    gn_apply_pack_k<<<dim3(HWP/256, 8, BB), 256>>>(x1, off_g1, off_b1, stats + 0*512,
                                                   128, 0, 4, 0, a2h, a2l, 0, 8);

    // conv2 (128 -> 64) -> stats; GN+SiLU fused into conv3
    conv3x3_mma_k<8,64><<<dim3(64, 1, BB), 256, SMEM_64>>>(a2h, a2l, wh + WOFF2, wl + WOFF2, x2, 64);
    gn_stats2_k<<<dim3(8, 256), 256>>>(x2, 64, 0, 2, red + 1*512);
    finalize_k<<<1, 256>>>(red + 1*512, stats + 1*512, 2*HWP);

    // conv3 (64 -> 3) + bias, GN+SiLU on x2 inline
    conv3_k<<<dim3(64, 1, BB), 256>>>(x2, off_w3, off_bias3, pred, off_g2, off_b2, stats + 1*512);

    // warp -> aligned + flow (into d_out)
    warp_k<<<BB*HWP/256, 256>>>(feat2, pred, out);

    // cost volume (3 dy-groups)
    costvol_k<<<dim3(64, 3, BB), 256>>>(feat1, out + ALIGNED_OFF, cv);

    // corr 1x1 (81 -> 64) into cd[0:64], diff 1x1 (128 -> 64) into cd[64:128]
    conv1x1_k<81, 0><<<BB*HWP/128, 256>>>(cv, nullptr, corr_w, cd, 0);
    conv1x1_k<128, 1><<<BB*HWP/128, 256>>>(feat1, out + ALIGNED_OFF, diff_w, cd, 64);

    // GN + relu on each half -> packed A3
    gn_stats2_k<<<dim3(8, 256), 256>>>(cd, 128, 0, 2, red + 2*512);
    gn_stats2_k<<<dim3(8, 256), 256>>>(cd, 128, 64, 2, red + 3*512);
    finalize_k<<<1, 256>>>(red + 2*512, stats + 2*512, 2*HWP);
    finalize_k<<<1, 256>>>(red + 3*512, stats + 3*512, 2*HWP);
    gn_apply_pack_k<<<dim3(HWP/256, 4, BB), 256>>>(cd, corr_g, corr_b, stats + 2*512,
                                                   128, 0, 2, 1, a3h, a3l, 0, 8);
    gn_apply_pack_k<<<dim3(HWP/256, 4, BB), 256>>>(cd, diff_g, diff_b, stats + 3*512,
                                                   128, 64, 2, 1, a3h, a3l, 4, 8);

    // fus1 (128 -> 128), raw f; GN fused into lam
    conv3x3_mma_k<8,128><<<dim3(64, 1, BB), 256, SMEM_128>>>(a3h, a3l, wh + WOFFF, wl + WOFFF, f, 128);
    gn_stats2_k<<<dim3(8, 256), 256>>>(f, 128, 0, 4, red + 4*512);
    finalize_k<<<1, 256>>>(red + 4*512, stats + 4*512, 4*HWP);

    // fused fus2 + GN + relu + lam
    weff_k<<<1, 128>>>(fus_w2, lam_w, weff);
    lam_gn_k<<<BB*HWP/256, 256>>>(f, weff, fus_g1, fus_b1, stats + 4*512, lam_b, out);
}